// round 2
// baseline (speedup 1.0000x reference)
#include <cuda_runtime.h>
#include <math.h>
#include <float.h>
#include <stdint.h>

// Problem constants
#define N_SRC   16384
#define M_ANC   8192
#define D_DIM   512
#define F_DIM   2048
#define KNN_K   5
#define BN_EPS  1e-5f

// ---------------------------------------------------------------------------
// Scratch (static device allocations; no cudaMalloc allowed)
// ---------------------------------------------------------------------------
__device__ float g_dots[(size_t)N_SRC * M_ANC];     // 512 MB
__device__ float g_anorm[M_ANC];
__device__ int   g_idx[N_SRC * KNN_K];
__device__ float g_neigh[(size_t)N_SRC * D_DIM];
__device__ float g_amap[(size_t)N_SRC * D_DIM];
__device__ float g_comb[(size_t)N_SRC * D_DIM];
__device__ float g_hidden[(size_t)N_SRC * F_DIM];   // 134 MB
__device__ float g_tbuf[(size_t)N_SRC * D_DIM];
__device__ float g_zbuf[(size_t)N_SRC * D_DIM];
__device__ float g_ps[128 * D_DIM];
__device__ float g_qs[128 * D_DIM];
__device__ float g_mean[D_DIM];
__device__ float g_rstd[D_DIM];

// ---------------------------------------------------------------------------
// anchor squared norms: one warp per row
// ---------------------------------------------------------------------------
__global__ void anorm_kernel(const float* __restrict__ anchor, float* __restrict__ anorm) {
    int gw = (blockIdx.x * blockDim.x + threadIdx.x) >> 5;
    int lane = threadIdx.x & 31;
    if (gw >= M_ANC) return;
    const float* row = anchor + (size_t)gw * D_DIM;
    float s = 0.f;
    #pragma unroll
    for (int j = lane; j < D_DIM; j += 32) { float v = row[j]; s += v * v; }
    #pragma unroll
    for (int off = 16; off; off >>= 1) s += __shfl_xor_sync(0xffffffffu, s, off);
    if (lane == 0) anorm[gw] = s;
}

// ---------------------------------------------------------------------------
// Generic fp32 SGEMM: C[M,N] = A[M,K] * op(B) (+bias) (+C) (tanh)
// TB: B is [N,K] row-major (B transposed, i.e. C = A * B^T). else B is [K,N].
// All dims must be multiples of the tile sizes (they are, for this problem).
// ---------------------------------------------------------------------------
#define BM 128
#define BN 128
#define BKK 16

template<bool TB, bool ACC, bool BIAS, bool TANH>
__global__ void __launch_bounds__(256, 2) gemm_kernel(
    const float* __restrict__ A, const float* __restrict__ B,
    const float* __restrict__ bias, float* __restrict__ C,
    int M, int N, int K)
{
    __shared__ float As[BKK][BM + 4];
    __shared__ float Bs[BKK][BN + 4];

    int tid = threadIdx.x;
    int bx = blockIdx.x;   // N-tile
    int by = blockIdx.y;   // M-tile

    const float* Ablk = A + (size_t)by * BM * K;
    const float* Bblk = TB ? (B + (size_t)bx * BN * K) : B;

    float acc[8][8];
    #pragma unroll
    for (int i = 0; i < 8; i++)
        #pragma unroll
        for (int j = 0; j < 8; j++) acc[i][j] = 0.f;

    int ar = tid >> 2;           // 0..63
    int ac = (tid & 3) << 2;     // 0,4,8,12
    int kb = tid >> 5;           // 0..7
    int nb = (tid & 31) << 2;    // 0..124

    int ty = tid >> 4, tx = tid & 15;

    for (int kt = 0; kt < K; kt += BKK) {
        #pragma unroll
        for (int i = 0; i < 2; i++) {
            int r = ar + i * 64;
            float4 v = *(const float4*)(Ablk + (size_t)r * K + kt + ac);
            As[ac + 0][r] = v.x; As[ac + 1][r] = v.y;
            As[ac + 2][r] = v.z; As[ac + 3][r] = v.w;
        }
        if (TB) {
            #pragma unroll
            for (int i = 0; i < 2; i++) {
                int r = ar + i * 64;
                float4 v = *(const float4*)(Bblk + (size_t)r * K + kt + ac);
                Bs[ac + 0][r] = v.x; Bs[ac + 1][r] = v.y;
                Bs[ac + 2][r] = v.z; Bs[ac + 3][r] = v.w;
            }
        } else {
            #pragma unroll
            for (int i = 0; i < 2; i++) {
                int kk = kb + i * 8;
                float4 v = *(const float4*)(B + (size_t)(kt + kk) * N + bx * BN + nb);
                *(float4*)&Bs[kk][nb] = v;
            }
        }
        __syncthreads();

        #pragma unroll
        for (int k = 0; k < BKK; k++) {
            float a[8], b[8];
            *(float4*)(a)     = *(float4*)&As[k][ty * 8];
            *(float4*)(a + 4) = *(float4*)&As[k][ty * 8 + 4];
            *(float4*)(b)     = *(float4*)&Bs[k][tx * 8];
            *(float4*)(b + 4) = *(float4*)&Bs[k][tx * 8 + 4];
            #pragma unroll
            for (int i = 0; i < 8; i++)
                #pragma unroll
                for (int j = 0; j < 8; j++)
                    acc[i][j] += a[i] * b[j];
        }
        __syncthreads();
    }

    int row0 = by * BM + ty * 8;
    int col0 = bx * BN + tx * 8;
    float bv[8];
    #pragma unroll
    for (int j = 0; j < 8; j++) bv[j] = BIAS ? bias[col0 + j] : 0.f;

    #pragma unroll
    for (int i = 0; i < 8; i++) {
        float* crow = C + (size_t)(row0 + i) * N + col0;
        #pragma unroll
        for (int jj = 0; jj < 2; jj++) {
            float4 old;
            if (ACC) old = *(float4*)(crow + jj * 4);
            float v0 = acc[i][jj * 4 + 0] + bv[jj * 4 + 0];
            float v1 = acc[i][jj * 4 + 1] + bv[jj * 4 + 1];
            float v2 = acc[i][jj * 4 + 2] + bv[jj * 4 + 2];
            float v3 = acc[i][jj * 4 + 3] + bv[jj * 4 + 3];
            if (ACC) { v0 += old.x; v1 += old.y; v2 += old.z; v3 += old.w; }
            if (TANH) { v0 = tanhf(v0); v1 = tanhf(v1); v2 = tanhf(v2); v3 = tanhf(v3); }
            *(float4*)(crow + jj * 4) = make_float4(v0, v1, v2, v3);
        }
    }
}

// ---------------------------------------------------------------------------
// top-5 smallest of (anorm[m] - 2*dot[n,m]) per row. One warp per row.
// ---------------------------------------------------------------------------
__global__ void topk_kernel(const float* __restrict__ dots,
                            const float* __restrict__ anorm,
                            int* __restrict__ idx_out)
{
    int row = (blockIdx.x * blockDim.x + threadIdx.x) >> 5;
    int lane = threadIdx.x & 31;
    if (row >= N_SRC) return;

    const float* drow = dots + (size_t)row * M_ANC;
    float best[KNN_K];
    int   bidx[KNN_K];
    #pragma unroll
    for (int i = 0; i < KNN_K; i++) { best[i] = FLT_MAX; bidx[i] = 0x7fffffff; }

    for (int m = lane; m < M_ANC; m += 32) {
        float d = anorm[m] - 2.f * drow[m];
        if (d < best[KNN_K - 1]) {
            int p = KNN_K - 1;
            #pragma unroll
            for (int q = KNN_K - 1; q > 0; q--) {
                if (d < best[q - 1]) { best[q] = best[q - 1]; bidx[q] = bidx[q - 1]; p = q - 1; }
            }
            best[p] = d; bidx[p] = m;
        }
    }

    // warp merge: 5 selection rounds
    int head = 0;
    #pragma unroll
    for (int s = 0; s < KNN_K; s++) {
        float v = (head < KNN_K) ? best[head] : FLT_MAX;
        int   id = (head < KNN_K) ? bidx[head] : 0x7fffffff;
        float mv = v; int mi = id;
        #pragma unroll
        for (int off = 16; off; off >>= 1) {
            float ov = __shfl_xor_sync(0xffffffffu, mv, off);
            int   oi = __shfl_xor_sync(0xffffffffu, mi, off);
            if (ov < mv || (ov == mv && oi < mi)) { mv = ov; mi = oi; }
        }
        if (head < KNN_K && bidx[head] == mi) head++;
        if (lane == 0) idx_out[row * KNN_K + s] = mi;
    }
}

// ---------------------------------------------------------------------------
// neigh[n,:] = mean of 5 gathered anchor rows. One thread per float4.
// ---------------------------------------------------------------------------
__global__ void gather_mean_kernel(const float* __restrict__ anchor,
                                   const int* __restrict__ idx,
                                   float* __restrict__ neigh)
{
    int i = blockIdx.x * blockDim.x + threadIdx.x;    // over N * D/4
    if (i >= N_SRC * (D_DIM / 4)) return;
    int n = i / (D_DIM / 4);
    int d4 = (i % (D_DIM / 4)) * 4;
    const int* ix = idx + n * KNN_K;
    float4 a = make_float4(0.f, 0.f, 0.f, 0.f);
    #pragma unroll
    for (int k = 0; k < KNN_K; k++) {
        float4 v = *(const float4*)(anchor + (size_t)ix[k] * D_DIM + d4);
        a.x += v.x; a.y += v.y; a.z += v.z; a.w += v.w;
    }
    const float inv = 1.f / (float)KNN_K;
    a.x *= inv; a.y *= inv; a.z *= inv; a.w *= inv;
    *(float4*)(neigh + (size_t)n * D_DIM + d4) = a;
}

// ---------------------------------------------------------------------------
// BatchNorm: deterministic 2-stage column reduction over N=16384 rows, C=512
// ---------------------------------------------------------------------------
__global__ void bn_stats_kernel(const float* __restrict__ X,
                                float* __restrict__ ps, float* __restrict__ qs)
{
    int c = threadIdx.x;                 // 512 threads
    int r0 = blockIdx.x * 128;           // 128 blocks
    float s = 0.f, q = 0.f;
    #pragma unroll 4
    for (int r = 0; r < 128; r++) {
        float v = X[(size_t)(r0 + r) * D_DIM + c];
        s += v; q += v * v;
    }
    ps[blockIdx.x * D_DIM + c] = s;
    qs[blockIdx.x * D_DIM + c] = q;
}

__global__ void bn_final_kernel(const float* __restrict__ ps, const float* __restrict__ qs,
                                float* __restrict__ mean, float* __restrict__ rstd)
{
    int c = threadIdx.x;
    float s = 0.f, q = 0.f;
    #pragma unroll 8
    for (int b = 0; b < 128; b++) { s += ps[b * D_DIM + c]; q += qs[b * D_DIM + c]; }
    float m = s * (1.f / (float)N_SRC);
    float v = q * (1.f / (float)N_SRC) - m * m;
    mean[c] = m;
    rstd[c] = rsqrtf(v + BN_EPS);
}

template<bool TANH>
__global__ void bn_apply_kernel(const float* __restrict__ X, float* __restrict__ Y,
                                const float* __restrict__ mean, const float* __restrict__ rstd,
                                const float* __restrict__ g, const float* __restrict__ b)
{
    int i = blockIdx.x * blockDim.x + threadIdx.x;    // over N*D/4
    if (i >= N_SRC * (D_DIM / 4)) return;
    int c0 = (i * 4) & (D_DIM - 1);
    float4 x = *(const float4*)(X + (size_t)i * 4);
    float v0 = (x.x - mean[c0 + 0]) * rstd[c0 + 0] * g[c0 + 0] + b[c0 + 0];
    float v1 = (x.y - mean[c0 + 1]) * rstd[c0 + 1] * g[c0 + 1] + b[c0 + 1];
    float v2 = (x.z - mean[c0 + 2]) * rstd[c0 + 2] * g[c0 + 2] + b[c0 + 2];
    float v3 = (x.w - mean[c0 + 3]) * rstd[c0 + 3] * g[c0 + 3] + b[c0 + 3];
    if (TANH) { v0 = tanhf(v0); v1 = tanhf(v1); v2 = tanhf(v2); v3 = tanhf(v3); }
    *(float4*)(Y + (size_t)i * 4) = make_float4(v0, v1, v2, v3);
}

__global__ void add_kernel(float* __restrict__ A, const float* __restrict__ B, int n4)
{
    int i = blockIdx.x * blockDim.x + threadIdx.x;
    if (i >= n4) return;
    float4 a = *(float4*)(A + (size_t)i * 4);
    float4 b = *(const float4*)(B + (size_t)i * 4);
    a.x += b.x; a.y += b.y; a.z += b.z; a.w += b.w;
    *(float4*)(A + (size_t)i * 4) = a;
}

// ---------------------------------------------------------------------------
// launch
// ---------------------------------------------------------------------------
extern "C" void kernel_launch(void* const* d_in, const int* in_sizes, int n_in,
                              void* d_out, int out_size)
{
    const float* src    = (const float*)d_in[0];
    const float* anchor = (const float*)d_in[1];
    const float* W_dim  = (const float*)d_in[2];
    const float* b_dim  = (const float*)d_in[3];
    const float* W_fus  = (const float*)d_in[4];
    const float* b_fus  = (const float*)d_in[5];
    const float* W_e1   = (const float*)d_in[6];
    const float* b_e1   = (const float*)d_in[7];
    const float* W_e2   = (const float*)d_in[8];
    const float* b_e2   = (const float*)d_in[9];
    const float* g1     = (const float*)d_in[10];
    const float* bt1    = (const float*)d_in[11];
    const float* g2     = (const float*)d_in[12];
    const float* bt2    = (const float*)d_in[13];
    const float* W_d    = (const float*)d_in[14];
    const float* b_d    = (const float*)d_in[15];
    const float* g_d    = (const float*)d_in[16];
    const float* bt_d   = (const float*)d_in[17];
    float* out = (float*)d_out;

    float *dots, *anorm, *neigh, *amap, *comb, *hidden, *tbuf, *zbuf;
    float *ps, *qs, *mean, *rstd;
    int* idx;
    cudaGetSymbolAddress((void**)&dots,   g_dots);
    cudaGetSymbolAddress((void**)&anorm,  g_anorm);
    cudaGetSymbolAddress((void**)&idx,    g_idx);
    cudaGetSymbolAddress((void**)&neigh,  g_neigh);
    cudaGetSymbolAddress((void**)&amap,   g_amap);
    cudaGetSymbolAddress((void**)&comb,   g_comb);
    cudaGetSymbolAddress((void**)&hidden, g_hidden);
    cudaGetSymbolAddress((void**)&tbuf,   g_tbuf);
    cudaGetSymbolAddress((void**)&zbuf,   g_zbuf);
    cudaGetSymbolAddress((void**)&ps,     g_ps);
    cudaGetSymbolAddress((void**)&qs,     g_qs);
    cudaGetSymbolAddress((void**)&mean,   g_mean);
    cudaGetSymbolAddress((void**)&rstd,   g_rstd);

    const int ND4 = N_SRC * (D_DIM / 4);

    // 1. anchor norms
    anorm_kernel<<<(M_ANC * 32 + 255) / 256, 256>>>(anchor, anorm);

    // 2. dots = src @ anchor^T   [16384 x 8192], K=512
    gemm_kernel<true, false, false, false><<<dim3(M_ANC / BN, N_SRC / BM), 256>>>(
        src, anchor, nullptr, dots, N_SRC, M_ANC, D_DIM);

    // 3. top-5 per row
    topk_kernel<<<(N_SRC * 32) / 256, 256>>>(dots, anorm, idx);

    // 4. gather + mean
    gather_mean_kernel<<<(ND4 + 255) / 256, 256>>>(anchor, idx, neigh);

    // 5. a_map = neigh @ W_dim + b_dim
    gemm_kernel<false, false, true, false><<<dim3(D_DIM / BN, N_SRC / BM), 256>>>(
        neigh, W_dim, b_dim, amap, N_SRC, D_DIM, D_DIM);

    // 6. comb = src @ W_fus[:512] + b_fus ; += a_map @ W_fus[512:]
    gemm_kernel<false, false, true, false><<<dim3(D_DIM / BN, N_SRC / BM), 256>>>(
        src, W_fus, b_fus, comb, N_SRC, D_DIM, D_DIM);
    gemm_kernel<false, true, false, false><<<dim3(D_DIM / BN, N_SRC / BM), 256>>>(
        amap, W_fus + (size_t)D_DIM * D_DIM, nullptr, comb, N_SRC, D_DIM, D_DIM);

    // 7. BN1 (in place)
    bn_stats_kernel<<<128, 512>>>(comb, ps, qs);
    bn_final_kernel<<<1, 512>>>(ps, qs, mean, rstd);
    bn_apply_kernel<false><<<(ND4 + 255) / 256, 256>>>(comb, comb, mean, rstd, g1, bt1);

    // 8. hidden = tanh(comb @ W_e1 + b_e1)
    gemm_kernel<false, false, true, true><<<dim3(F_DIM / BN, N_SRC / BM), 256>>>(
        comb, W_e1, b_e1, hidden, N_SRC, F_DIM, D_DIM);

    // 9. tbuf = hidden @ W_e2 + b_e2
    gemm_kernel<false, false, true, false><<<dim3(D_DIM / BN, N_SRC / BM), 256>>>(
        hidden, W_e2, b_e2, tbuf, N_SRC, D_DIM, F_DIM);

    // 10. comb += tbuf ; BN2 in place
    add_kernel<<<(ND4 + 255) / 256, 256>>>(comb, tbuf, ND4);
    bn_stats_kernel<<<128, 512>>>(comb, ps, qs);
    bn_final_kernel<<<1, 512>>>(ps, qs, mean, rstd);
    bn_apply_kernel<false><<<(ND4 + 255) / 256, 256>>>(comb, comb, mean, rstd, g2, bt2);

    // 11. zbuf = comb @ W_d + b_d ; out = tanh(BN(zbuf))
    gemm_kernel<false, false, true, false><<<dim3(D_DIM / BN, N_SRC / BM), 256>>>(
        comb, W_d, b_d, zbuf, N_SRC, D_DIM, D_DIM);
    bn_stats_kernel<<<128, 512>>>(zbuf, ps, qs);
    bn_final_kernel<<<1, 512>>>(ps, qs, mean, rstd);
    bn_apply_kernel<true><<<(ND4 + 255) / 256, 256>>>(zbuf, out, mean, rstd, g_d, bt_d);
}

// round 5
// speedup vs baseline: 1.2088x; 1.2088x over previous
#include <cuda_runtime.h>
#include <math.h>
#include <float.h>
#include <stdint.h>

// Problem constants
#define N_SRC   16384
#define M_ANC   8192
#define D_DIM   512
#define F_DIM   2048
#define KNN_K   5
#define BN_EPS  1e-5f

// ---------------------------------------------------------------------------
// Scratch (static device allocations; no cudaMalloc allowed)
// ---------------------------------------------------------------------------
__device__ float g_dots[(size_t)N_SRC * M_ANC];     // 512 MB
__device__ float g_anorm[M_ANC];
__device__ int   g_idx[N_SRC * KNN_K];
__device__ float g_neigh[(size_t)N_SRC * D_DIM];
__device__ float g_amap[(size_t)N_SRC * D_DIM];
__device__ float g_comb[(size_t)N_SRC * D_DIM];
__device__ float g_hidden[(size_t)N_SRC * F_DIM];   // 134 MB
__device__ float g_tbuf[(size_t)N_SRC * D_DIM];
__device__ float g_zbuf[(size_t)N_SRC * D_DIM];
__device__ float g_ps[128 * D_DIM];
__device__ float g_qs[128 * D_DIM];
__device__ float g_mean[D_DIM];
__device__ float g_rstd[D_DIM];

// ===========================================================================
// Distance GEMM via mma.sync tf32 (sm_80+ PTX — works at compute_103):
//   C[N_SRC, M_ANC] = src @ anchor^T
// CTA tile 128x128, 8 warps as 2(M) x 4(N), each warp 64x32.
// ===========================================================================
__device__ __forceinline__ void mma_tf32(float* c, const uint32_t* a, const uint32_t* b)
{
    asm volatile(
        "mma.sync.aligned.m16n8k8.row.col.f32.tf32.tf32.f32 "
        "{%0,%1,%2,%3}, {%4,%5,%6,%7}, {%8,%9}, {%0,%1,%2,%3};"
        : "+f"(c[0]), "+f"(c[1]), "+f"(c[2]), "+f"(c[3])
        : "r"(a[0]), "r"(a[1]), "r"(a[2]), "r"(a[3]),
          "r"(b[0]), "r"(b[1]));
}

__global__ void __launch_bounds__(256, 2) dist_gemm_kernel(
    const float* __restrict__ A,   // src    [N_SRC, 512]
    const float* __restrict__ B,   // anchor [M_ANC, 512]
    float* __restrict__ C)         // dots   [N_SRC, M_ANC]
{
    __shared__ float sA[2][2048];
    __shared__ float sB[2][2048];

    int tid = threadIdx.x;
    int lane = tid & 31;
    int wid = tid >> 5;
    int warp_m = wid >> 2;     // 0..1
    int warp_n = wid & 3;      // 0..3
    int bx = blockIdx.x;       // anchor tile
    int by = blockIdx.y;       // src tile

    const float* Ab = A + (size_t)(by * 128) * D_DIM;
    const float* Bb = B + (size_t)(bx * 128) * D_DIM;

    float acc[4][4][4];
    #pragma unroll
    for (int i = 0; i < 4; i++)
        #pragma unroll
        for (int j = 0; j < 4; j++)
            #pragma unroll
            for (int e = 0; e < 4; e++) acc[i][j][e] = 0.f;

    int r  = tid >> 1;
    int c0 = (tid & 1) * 8;
    int mtile = r >> 4, rr = r & 15;
    int ntile = r >> 3, nn = r & 7;

    float4 av[2], bv[2];

    #pragma unroll
    for (int j = 0; j < 2; j++) {
        av[j] = *(const float4*)(Ab + (size_t)r * D_DIM + c0 + j * 4);
        bv[j] = *(const float4*)(Bb + (size_t)r * D_DIM + c0 + j * 4);
    }
    #pragma unroll
    for (int j = 0; j < 2; j++) {
        float aval[4] = {av[j].x, av[j].y, av[j].z, av[j].w};
        float bval[4] = {bv[j].x, bv[j].y, bv[j].z, bv[j].w};
        #pragma unroll
        for (int e = 0; e < 4; e++) {
            int k = c0 + j * 4 + e;
            int kstep = k >> 3, kk = k & 7;
            int aoff = (((mtile * 2 + kstep) * 32) + ((rr & 7) * 4 + (kk & 3))) * 4
                       + (rr >> 3) + 2 * (kk >> 2);
            sA[0][aoff] = aval[e];
            int boff = (((ntile * 2 + kstep) * 32) + (nn * 4 + (kk & 3))) * 2 + (kk >> 2);
            sB[0][boff] = bval[e];
        }
    }
    __syncthreads();

    const int KIT = D_DIM / 16;    // 32
    for (int it = 0; it < KIT; it++) {
        int cur = it & 1;

        if (it + 1 < KIT) {
            int kt = (it + 1) * 16;
            #pragma unroll
            for (int j = 0; j < 2; j++) {
                av[j] = *(const float4*)(Ab + (size_t)r * D_DIM + kt + c0 + j * 4);
                bv[j] = *(const float4*)(Bb + (size_t)r * D_DIM + kt + c0 + j * 4);
            }
        }

        #pragma unroll
        for (int ks = 0; ks < 2; ks++) {
            uint32_t af[4][4], bf[4][2];
            #pragma unroll
            for (int i = 0; i < 4; i++) {
                const uint4* p = (const uint4*)&sA[cur][(((warp_m * 4 + i) * 2 + ks) * 32 + lane) * 4];
                uint4 v = *p;
                af[i][0] = v.x; af[i][1] = v.y; af[i][2] = v.z; af[i][3] = v.w;
            }
            #pragma unroll
            for (int j = 0; j < 4; j++) {
                const uint2* p = (const uint2*)&sB[cur][(((warp_n * 4 + j) * 2 + ks) * 32 + lane) * 2];
                uint2 v = *p;
                bf[j][0] = v.x; bf[j][1] = v.y;
            }
            #pragma unroll
            for (int i = 0; i < 4; i++)
                #pragma unroll
                for (int j = 0; j < 4; j++)
                    mma_tf32(acc[i][j], af[i], bf[j]);
        }

        if (it + 1 < KIT) {
            int nxt = cur ^ 1;
            #pragma unroll
            for (int j = 0; j < 2; j++) {
                float aval[4] = {av[j].x, av[j].y, av[j].z, av[j].w};
                float bval[4] = {bv[j].x, bv[j].y, bv[j].z, bv[j].w};
                #pragma unroll
                for (int e = 0; e < 4; e++) {
                    int k = c0 + j * 4 + e;
                    int kstep = k >> 3, kk = k & 7;
                    int aoff = (((mtile * 2 + kstep) * 32) + ((rr & 7) * 4 + (kk & 3))) * 4
                               + (rr >> 3) + 2 * (kk >> 2);
                    sA[nxt][aoff] = aval[e];
                    int boff = (((ntile * 2 + kstep) * 32) + (nn * 4 + (kk & 3))) * 2 + (kk >> 2);
                    sB[nxt][boff] = bval[e];
                }
            }
            __syncthreads();
        }
    }

    int row0 = by * 128 + warp_m * 64;
    int col0 = bx * 128 + warp_n * 32;
    #pragma unroll
    for (int i = 0; i < 4; i++) {
        int ra = row0 + i * 16 + (lane >> 2);
        #pragma unroll
        for (int j = 0; j < 4; j++) {
            int ca = col0 + j * 8 + (lane & 3) * 2;
            *(float2*)(C + (size_t)ra * M_ANC + ca) =
                make_float2(acc[i][j][0], acc[i][j][1]);
            *(float2*)(C + (size_t)(ra + 8) * M_ANC + ca) =
                make_float2(acc[i][j][2], acc[i][j][3]);
        }
    }
}

// ---------------------------------------------------------------------------
// anchor squared norms: one warp per row
// ---------------------------------------------------------------------------
__global__ void anorm_kernel(const float* __restrict__ anchor, float* __restrict__ anorm) {
    int gw = (blockIdx.x * blockDim.x + threadIdx.x) >> 5;
    int lane = threadIdx.x & 31;
    if (gw >= M_ANC) return;
    const float* row = anchor + (size_t)gw * D_DIM;
    float s = 0.f;
    #pragma unroll
    for (int j = lane; j < D_DIM; j += 32) { float v = row[j]; s += v * v; }
    #pragma unroll
    for (int off = 16; off; off >>= 1) s += __shfl_xor_sync(0xffffffffu, s, off);
    if (lane == 0) anorm[gw] = s;
}

// ---------------------------------------------------------------------------
// top-5 with tf32->fp32 refinement. One warp per row.
// Pass 1: approx top-5 -> threshold. Pass 2: collect candidates within margin.
// Pass 3: exact fp32 distances for candidates, exact (value,idx) top-5.
// ---------------------------------------------------------------------------
#define TK_MARGIN 1.0f
#define TK_MAXC   64

__global__ void __launch_bounds__(256) topk_refine_kernel(
    const float* __restrict__ dots,
    const float* __restrict__ anorm,
    const float* __restrict__ src,
    const float* __restrict__ anchor,
    int* __restrict__ idx_out)
{
    __shared__ int   s_cand[8][TK_MAXC];
    __shared__ float s_dval[8][TK_MAXC];

    int w = threadIdx.x >> 5;
    int row = (blockIdx.x * blockDim.x + threadIdx.x) >> 5;
    int lane = threadIdx.x & 31;
    if (row >= N_SRC) return;

    const float* drow = dots + (size_t)row * M_ANC;

    // ---- pass 1: lane-local approx top-5, then merge for 5th value ----
    float best[KNN_K];
    int   bidx[KNN_K];
    #pragma unroll
    for (int i = 0; i < KNN_K; i++) { best[i] = FLT_MAX; bidx[i] = 0x7fffffff; }

    for (int m = lane; m < M_ANC; m += 32) {
        float d = anorm[m] - 2.f * drow[m];
        if (d < best[KNN_K - 1]) {
            int p = KNN_K - 1;
            #pragma unroll
            for (int q = KNN_K - 1; q > 0; q--) {
                if (d < best[q - 1]) { best[q] = best[q - 1]; bidx[q] = bidx[q - 1]; p = q - 1; }
            }
            best[p] = d; bidx[p] = m;
        }
    }

    float t5 = FLT_MAX;
    int head = 0;
    #pragma unroll
    for (int s = 0; s < KNN_K; s++) {
        float mv = (head < KNN_K) ? best[head] : FLT_MAX;
        int   mi = (head < KNN_K) ? bidx[head] : 0x7fffffff;
        #pragma unroll
        for (int off = 16; off; off >>= 1) {
            float ov = __shfl_xor_sync(0xffffffffu, mv, off);
            int   oi = __shfl_xor_sync(0xffffffffu, mi, off);
            if (ov < mv || (ov == mv && oi < mi)) { mv = ov; mi = oi; }
        }
        if (head < KNN_K && bidx[head] == mi) head++;
        t5 = mv;                           // after last round: 5th value
    }
    float thresh = t5 + TK_MARGIN;

    // ---- pass 2: collect candidate indices (compacted via ballot) ----
    int cnt = 0;
    for (int m = lane; m < M_ANC; m += 32) {
        float d = anorm[m] - 2.f * drow[m];
        bool pred = (d <= thresh);
        unsigned mask = __ballot_sync(0xffffffffu, pred);
        if (pred) {
            int pos = cnt + __popc(mask & ((1u << lane) - 1u));
            if (pos < TK_MAXC) s_cand[w][pos] = m;
        }
        cnt += __popc(mask);
    }
    if (cnt > TK_MAXC) cnt = TK_MAXC;
    __syncwarp();

    // ---- pass 3: exact fp32 distances for candidates ----
    float sreg[D_DIM / 32];
    const float* srow = src + (size_t)row * D_DIM;
    #pragma unroll
    for (int j = 0; j < D_DIM / 32; j++) sreg[j] = srow[lane + 32 * j];

    for (int c = 0; c < cnt; c++) {
        int m = s_cand[w][c];
        const float* arow = anchor + (size_t)m * D_DIM;
        float s = 0.f;
        #pragma unroll
        for (int j = 0; j < D_DIM / 32; j++) s += sreg[j] * arow[lane + 32 * j];
        #pragma unroll
        for (int off = 16; off; off >>= 1) s += __shfl_xor_sync(0xffffffffu, s, off);
        if (lane == 0) s_dval[w][c] = anorm[m] - 2.f * s;
    }
    __syncwarp();

    // ---- final: serial exact (value, idx) top-5 on lane 0 ----
    if (lane == 0) {
        #pragma unroll
        for (int s = 0; s < KNN_K; s++) {
            float mv = FLT_MAX; int mi = 0x7fffffff; int mc = -1;
            for (int c = 0; c < cnt; c++) {
                float v = s_dval[w][c]; int id = s_cand[w][c];
                if (v < mv || (v == mv && id < mi)) { mv = v; mi = id; mc = c; }
            }
            idx_out[row * KNN_K + s] = mi;
            if (mc >= 0) s_dval[w][mc] = FLT_MAX;
        }
    }
}

// ---------------------------------------------------------------------------
// Generic fp32 SGEMM: C[M,N] = A[M,K] * op(B) (+bias) (+C) (tanh)
// ---------------------------------------------------------------------------
#define BM 128
#define BN 128
#define BKK 16

template<bool TB, bool ACC, bool BIAS, bool TANH>
__global__ void __launch_bounds__(256, 2) gemm_kernel(
    const float* __restrict__ A, const float* __restrict__ B,
    const float* __restrict__ bias, float* __restrict__ C,
    int M, int N, int K)
{
    __shared__ float As[BKK][BM + 4];
    __shared__ float Bs[BKK][BN + 4];

    int tid = threadIdx.x;
    int bx = blockIdx.x;
    int by = blockIdx.y;

    const float* Ablk = A + (size_t)by * BM * K;
    const float* Bblk = TB ? (B + (size_t)bx * BN * K) : B;

    float acc[8][8];
    #pragma unroll
    for (int i = 0; i < 8; i++)
        #pragma unroll
        for (int j = 0; j < 8; j++) acc[i][j] = 0.f;

    int ar = tid >> 2;
    int ac = (tid & 3) << 2;
    int kb = tid >> 5;
    int nb = (tid & 31) << 2;

    int ty = tid >> 4, tx = tid & 15;

    for (int kt = 0; kt < K; kt += BKK) {
        #pragma unroll
        for (int i = 0; i < 2; i++) {
            int r = ar + i * 64;
            float4 v = *(const float4*)(Ablk + (size_t)r * K + kt + ac);
            As[ac + 0][r] = v.x; As[ac + 1][r] = v.y;
            As[ac + 2][r] = v.z; As[ac + 3][r] = v.w;
        }
        if (TB) {
            #pragma unroll
            for (int i = 0; i < 2; i++) {
                int r = ar + i * 64;
                float4 v = *(const float4*)(Bblk + (size_t)r * K + kt + ac);
                Bs[ac + 0][r] = v.x; Bs[ac + 1][r] = v.y;
                Bs[ac + 2][r] = v.z; Bs[ac + 3][r] = v.w;
            }
        } else {
            #pragma unroll
            for (int i = 0; i < 2; i++) {
                int kk = kb + i * 8;
                float4 v = *(const float4*)(B + (size_t)(kt + kk) * N + bx * BN + nb);
                *(float4*)&Bs[kk][nb] = v;
            }
        }
        __syncthreads();

        #pragma unroll
        for (int k = 0; k < BKK; k++) {
            float a[8], b[8];
            *(float4*)(a)     = *(float4*)&As[k][ty * 8];
            *(float4*)(a + 4) = *(float4*)&As[k][ty * 8 + 4];
            *(float4*)(b)     = *(float4*)&Bs[k][tx * 8];
            *(float4*)(b + 4) = *(float4*)&Bs[k][tx * 8 + 4];
            #pragma unroll
            for (int i = 0; i < 8; i++)
                #pragma unroll
                for (int j = 0; j < 8; j++)
                    acc[i][j] += a[i] * b[j];
        }
        __syncthreads();
    }

    int row0 = by * BM + ty * 8;
    int col0 = bx * BN + tx * 8;
    float bv[8];
    #pragma unroll
    for (int j = 0; j < 8; j++) bv[j] = BIAS ? bias[col0 + j] : 0.f;

    #pragma unroll
    for (int i = 0; i < 8; i++) {
        float* crow = C + (size_t)(row0 + i) * N + col0;
        #pragma unroll
        for (int jj = 0; jj < 2; jj++) {
            float4 old;
            if (ACC) old = *(float4*)(crow + jj * 4);
            float v0 = acc[i][jj * 4 + 0] + bv[jj * 4 + 0];
            float v1 = acc[i][jj * 4 + 1] + bv[jj * 4 + 1];
            float v2 = acc[i][jj * 4 + 2] + bv[jj * 4 + 2];
            float v3 = acc[i][jj * 4 + 3] + bv[jj * 4 + 3];
            if (ACC) { v0 += old.x; v1 += old.y; v2 += old.z; v3 += old.w; }
            if (TANH) { v0 = tanhf(v0); v1 = tanhf(v1); v2 = tanhf(v2); v3 = tanhf(v3); }
            *(float4*)(crow + jj * 4) = make_float4(v0, v1, v2, v3);
        }
    }
}

// ---------------------------------------------------------------------------
// neigh[n,:] = mean of 5 gathered anchor rows.
// ---------------------------------------------------------------------------
__global__ void gather_mean_kernel(const float* __restrict__ anchor,
                                   const int* __restrict__ idx,
                                   float* __restrict__ neigh)
{
    int i = blockIdx.x * blockDim.x + threadIdx.x;
    if (i >= N_SRC * (D_DIM / 4)) return;
    int n = i / (D_DIM / 4);
    int d4 = (i % (D_DIM / 4)) * 4;
    const int* ix = idx + n * KNN_K;
    float4 a = make_float4(0.f, 0.f, 0.f, 0.f);
    #pragma unroll
    for (int k = 0; k < KNN_K; k++) {
        float4 v = *(const float4*)(anchor + (size_t)ix[k] * D_DIM + d4);
        a.x += v.x; a.y += v.y; a.z += v.z; a.w += v.w;
    }
    const float inv = 1.f / (float)KNN_K;
    a.x *= inv; a.y *= inv; a.z *= inv; a.w *= inv;
    *(float4*)(neigh + (size_t)n * D_DIM + d4) = a;
}

// ---------------------------------------------------------------------------
// BatchNorm: deterministic 2-stage column reduction
// ---------------------------------------------------------------------------
__global__ void bn_stats_kernel(const float* __restrict__ X,
                                float* __restrict__ ps, float* __restrict__ qs)
{
    int c = threadIdx.x;
    int r0 = blockIdx.x * 128;
    float s = 0.f, q = 0.f;
    #pragma unroll 4
    for (int r = 0; r < 128; r++) {
        float v = X[(size_t)(r0 + r) * D_DIM + c];
        s += v; q += v * v;
    }
    ps[blockIdx.x * D_DIM + c] = s;
    qs[blockIdx.x * D_DIM + c] = q;
}

__global__ void bn_final_kernel(const float* __restrict__ ps, const float* __restrict__ qs,
                                float* __restrict__ mean, float* __restrict__ rstd)
{
    int c = threadIdx.x;
    float s = 0.f, q = 0.f;
    #pragma unroll 8
    for (int b = 0; b < 128; b++) { s += ps[b * D_DIM + c]; q += qs[b * D_DIM + c]; }
    float m = s * (1.f / (float)N_SRC);
    float v = q * (1.f / (float)N_SRC) - m * m;
    mean[c] = m;
    rstd[c] = rsqrtf(v + BN_EPS);
}

template<bool TANH>
__global__ void bn_apply_kernel(const float* __restrict__ X, float* __restrict__ Y,
                                const float* __restrict__ mean, const float* __restrict__ rstd,
                                const float* __restrict__ g, const float* __restrict__ b)
{
    int i = blockIdx.x * blockDim.x + threadIdx.x;
    if (i >= N_SRC * (D_DIM / 4)) return;
    int c0 = (i * 4) & (D_DIM - 1);
    float4 x = *(const float4*)(X + (size_t)i * 4);
    float v0 = (x.x - mean[c0 + 0]) * rstd[c0 + 0] * g[c0 + 0] + b[c0 + 0];
    float v1 = (x.y - mean[c0 + 1]) * rstd[c0 + 1] * g[c0 + 1] + b[c0 + 1];
    float v2 = (x.z - mean[c0 + 2]) * rstd[c0 + 2] * g[c0 + 2] + b[c0 + 2];
    float v3 = (x.w - mean[c0 + 3]) * rstd[c0 + 3] * g[c0 + 3] + b[c0 + 3];
    if (TANH) { v0 = tanhf(v0); v1 = tanhf(v1); v2 = tanhf(v2); v3 = tanhf(v3); }
    *(float4*)(Y + (size_t)i * 4) = make_float4(v0, v1, v2, v3);
}

__global__ void add_kernel(float* __restrict__ A, const float* __restrict__ B, int n4)
{
    int i = blockIdx.x * blockDim.x + threadIdx.x;
    if (i >= n4) return;
    float4 a = *(float4*)(A + (size_t)i * 4);
    float4 b = *(const float4*)(B + (size_t)i * 4);
    a.x += b.x; a.y += b.y; a.z += b.z; a.w += b.w;
    *(float4*)(A + (size_t)i * 4) = a;
}

// ---------------------------------------------------------------------------
// launch
// ---------------------------------------------------------------------------
extern "C" void kernel_launch(void* const* d_in, const int* in_sizes, int n_in,
                              void* d_out, int out_size)
{
    const float* src    = (const float*)d_in[0];
    const float* anchor = (const float*)d_in[1];
    const float* W_dim  = (const float*)d_in[2];
    const float* b_dim  = (const float*)d_in[3];
    const float* W_fus  = (const float*)d_in[4];
    const float* b_fus  = (const float*)d_in[5];
    const float* W_e1   = (const float*)d_in[6];
    const float* b_e1   = (const float*)d_in[7];
    const float* W_e2   = (const float*)d_in[8];
    const float* b_e2   = (const float*)d_in[9];
    const float* g1     = (const float*)d_in[10];
    const float* bt1    = (const float*)d_in[11];
    const float* g2     = (const float*)d_in[12];
    const float* bt2    = (const float*)d_in[13];
    const float* W_d    = (const float*)d_in[14];
    const float* b_d    = (const float*)d_in[15];
    const float* g_d    = (const float*)d_in[16];
    const float* bt_d   = (const float*)d_in[17];
    float* out = (float*)d_out;

    float *dots, *anorm, *neigh, *amap, *comb, *hidden, *tbuf, *zbuf;
    float *ps, *qs, *mean, *rstd;
    int* idx;
    cudaGetSymbolAddress((void**)&dots,   g_dots);
    cudaGetSymbolAddress((void**)&anorm,  g_anorm);
    cudaGetSymbolAddress((void**)&idx,    g_idx);
    cudaGetSymbolAddress((void**)&neigh,  g_neigh);
    cudaGetSymbolAddress((void**)&amap,   g_amap);
    cudaGetSymbolAddress((void**)&comb,   g_comb);
    cudaGetSymbolAddress((void**)&hidden, g_hidden);
    cudaGetSymbolAddress((void**)&tbuf,   g_tbuf);
    cudaGetSymbolAddress((void**)&zbuf,   g_zbuf);
    cudaGetSymbolAddress((void**)&ps,     g_ps);
    cudaGetSymbolAddress((void**)&qs,     g_qs);
    cudaGetSymbolAddress((void**)&mean,   g_mean);
    cudaGetSymbolAddress((void**)&rstd,   g_rstd);

    const int ND4 = N_SRC * (D_DIM / 4);

    // 1. anchor norms
    anorm_kernel<<<(M_ANC * 32 + 255) / 256, 256>>>(anchor, anorm);

    // 2. dots = src @ anchor^T on tensor cores (mma.sync tf32)
    dist_gemm_kernel<<<dim3(M_ANC / 128, N_SRC / 128), 256>>>(src, anchor, dots);

    // 3. top-5 per row with fp32 refinement
    topk_refine_kernel<<<(N_SRC * 32) / 256, 256>>>(dots, anorm, src, anchor, idx);

    // 4. gather + mean
    gather_mean_kernel<<<(ND4 + 255) / 256, 256>>>(anchor, idx, neigh);

    // 5. a_map = neigh @ W_dim + b_dim
    gemm_kernel<false, false, true, false><<<dim3(D_DIM / BN, N_SRC / BM), 256>>>(
        neigh, W_dim, b_dim, amap, N_SRC, D_DIM, D_DIM);

    // 6. comb = src @ W_fus[:512] + b_fus ; += a_map @ W_fus[512:]
    gemm_kernel<false, false, true, false><<<dim3(D_DIM / BN, N_SRC / BM), 256>>>(
        src, W_fus, b_fus, comb, N_SRC, D_DIM, D_DIM);
    gemm_kernel<false, true, false, false><<<dim3(D_DIM / BN, N_SRC / BM), 256>>>(
        amap, W_fus + (size_t)D_DIM * D_DIM, nullptr, comb, N_SRC, D_DIM, D_DIM);

    // 7. BN1 (in place)
    bn_stats_kernel<<<128, 512>>>(comb, ps, qs);
    bn_final_kernel<<<1, 512>>>(ps, qs, mean, rstd);
    bn_apply_kernel<false><<<(ND4 + 255) / 256, 256>>>(comb, comb, mean, rstd, g1, bt1);

    // 8. hidden = tanh(comb @ W_e1 + b_e1)
    gemm_kernel<false, false, true, true><<<dim3(F_DIM / BN, N_SRC / BM), 256>>>(
        comb, W_e1, b_e1, hidden, N_SRC, F_DIM, D_DIM);

    // 9. tbuf = hidden @ W_e2 + b_e2
    gemm_kernel<false, false, true, false><<<dim3(D_DIM / BN, N_SRC / BM), 256>>>(
        hidden, W_e2, b_e2, tbuf, N_SRC, D_DIM, F_DIM);

    // 10. comb += tbuf ; BN2 in place
    add_kernel<<<(ND4 + 255) / 256, 256>>>(comb, tbuf, ND4);
    bn_stats_kernel<<<128, 512>>>(comb, ps, qs);
    bn_final_kernel<<<1, 512>>>(ps, qs, mean, rstd);
    bn_apply_kernel<false><<<(ND4 + 255) / 256, 256>>>(comb, comb, mean, rstd, g2, bt2);

    // 11. zbuf = comb @ W_d + b_d ; out = tanh(BN(zbuf))
    gemm_kernel<false, false, true, false><<<dim3(D_DIM / BN, N_SRC / BM), 256>>>(
        comb, W_d, b_d, zbuf, N_SRC, D_DIM, D_DIM);
    bn_stats_kernel<<<128, 512>>>(zbuf, ps, qs);
    bn_final_kernel<<<1, 512>>>(ps, qs, mean, rstd);
    bn_apply_kernel<true><<<(ND4 + 255) / 256, 256>>>(zbuf, out, mean, rstd, g_d, bt_d);
}

// round 7
// speedup vs baseline: 1.5458x; 1.2788x over previous
#include <cuda_runtime.h>
#include <cuda_bf16.h>
#include <math.h>
#include <float.h>
#include <stdint.h>

// Problem constants
#define N_SRC   16384
#define M_ANC   8192
#define D_DIM   512
#define F_DIM   2048
#define KNN_K   5
#define BN_EPS  1e-5f

// ---------------------------------------------------------------------------
// Scratch (static device allocations; no cudaMalloc allowed)
// ---------------------------------------------------------------------------
__device__ float g_dots[(size_t)N_SRC * M_ANC];     // 512 MB
__device__ float g_anorm[M_ANC];
__device__ int   g_idx[N_SRC * KNN_K];
__device__ float g_neigh[(size_t)N_SRC * D_DIM];
__device__ float g_amap[(size_t)N_SRC * D_DIM];
__device__ float g_comb[(size_t)N_SRC * D_DIM];
__device__ float g_hidden[(size_t)N_SRC * F_DIM];   // 134 MB
__device__ float g_tbuf[(size_t)N_SRC * D_DIM];
__device__ float g_zbuf[(size_t)N_SRC * D_DIM];
__device__ float g_ps[128 * D_DIM];
__device__ float g_qs[128 * D_DIM];
__device__ float g_mean[D_DIM];
__device__ float g_rstd[D_DIM];
__device__ __nv_bfloat16 g_src_bf[(size_t)N_SRC * D_DIM];
__device__ __nv_bfloat16 g_anc_bf[(size_t)M_ANC * D_DIM];

// ---------------------------------------------------------------------------
// fp32 -> bf16 conversion (vectorized)
// ---------------------------------------------------------------------------
__global__ void tobf16_kernel(const float* __restrict__ x,
                              __nv_bfloat16* __restrict__ y, int n4)
{
    int i = blockIdx.x * blockDim.x + threadIdx.x;
    if (i >= n4) return;
    float4 v = *(const float4*)(x + (size_t)i * 4);
    __nv_bfloat162* o = (__nv_bfloat162*)(y + (size_t)i * 4);
    o[0] = __floats2bfloat162_rn(v.x, v.y);
    o[1] = __floats2bfloat162_rn(v.z, v.w);
}

// ===========================================================================
// Distance GEMM via bf16 ldmatrix + mma.sync m16n8k16:
//   C[N_SRC, M_ANC] = src_bf @ anc_bf^T   (fp32 accumulate)
// CTA 128x128, 8 warps 2(M)x4(N), warp tile 64x32, BK=32, double buffered.
// SMEM rows padded to 80B (40 bf16) -> conflict-free ldmatrix.
// ===========================================================================
#define DB_STRIDE 40   // bf16 per smem row (80 bytes)

__device__ __forceinline__ void mma_bf16(float* c, const uint32_t* a, const uint32_t* b)
{
    asm volatile(
        "mma.sync.aligned.m16n8k16.row.col.f32.bf16.bf16.f32 "
        "{%0,%1,%2,%3}, {%4,%5,%6,%7}, {%8,%9}, {%0,%1,%2,%3};"
        : "+f"(c[0]), "+f"(c[1]), "+f"(c[2]), "+f"(c[3])
        : "r"(a[0]), "r"(a[1]), "r"(a[2]), "r"(a[3]),
          "r"(b[0]), "r"(b[1]));
}

__device__ __forceinline__ void ldmatrix_x4(uint32_t* r, uint32_t saddr)
{
    asm volatile("ldmatrix.sync.aligned.m8n8.x4.shared.b16 {%0,%1,%2,%3}, [%4];"
                 : "=r"(r[0]), "=r"(r[1]), "=r"(r[2]), "=r"(r[3]) : "r"(saddr));
}

__device__ __forceinline__ void ldmatrix_x2(uint32_t* r, uint32_t saddr)
{
    asm volatile("ldmatrix.sync.aligned.m8n8.x2.shared.b16 {%0,%1}, [%2];"
                 : "=r"(r[0]), "=r"(r[1]) : "r"(saddr));
}

__global__ void __launch_bounds__(256, 2) dist_gemm_bf16_kernel(
    const __nv_bfloat16* __restrict__ A,   // src_bf [N_SRC, 512]
    const __nv_bfloat16* __restrict__ B,   // anc_bf [M_ANC, 512]
    float* __restrict__ C)                 // dots   [N_SRC, M_ANC]
{
    __shared__ __nv_bfloat16 sA[2][128 * DB_STRIDE];
    __shared__ __nv_bfloat16 sB[2][128 * DB_STRIDE];

    int tid = threadIdx.x;
    int lane = tid & 31;
    int wid = tid >> 5;
    int warp_m = wid >> 2;     // 0..1
    int warp_n = wid & 3;      // 0..3
    int bx = blockIdx.x;       // anchor tile
    int by = blockIdx.y;       // src tile

    const __nv_bfloat16* Ag = A + (size_t)(by * 128) * D_DIM;
    const __nv_bfloat16* Bg = B + (size_t)(bx * 128) * D_DIM;

    float acc[4][4][4];
    #pragma unroll
    for (int i = 0; i < 4; i++)
        #pragma unroll
        for (int j = 0; j < 4; j++)
            #pragma unroll
            for (int e = 0; e < 4; e++) acc[i][j][e] = 0.f;

    // loader geometry: thread t -> row t&127, two 16B quarters {t>>7, (t>>7)+2}
    int lr = tid & 127;
    int lq0 = tid >> 7;          // 0/1
    int lq1 = lq0 + 2;

    uint32_t a_s[2], b_s[2];
    a_s[0] = (uint32_t)__cvta_generic_to_shared(&sA[0][0]);
    a_s[1] = (uint32_t)__cvta_generic_to_shared(&sA[1][0]);
    b_s[0] = (uint32_t)__cvta_generic_to_shared(&sB[0][0]);
    b_s[1] = (uint32_t)__cvta_generic_to_shared(&sB[1][0]);

    // prologue: fill buffer 0 with kt=0
    {
        uint4 va0 = *(const uint4*)(Ag + (size_t)lr * D_DIM + lq0 * 8);
        uint4 va1 = *(const uint4*)(Ag + (size_t)lr * D_DIM + lq1 * 8);
        uint4 vb0 = *(const uint4*)(Bg + (size_t)lr * D_DIM + lq0 * 8);
        uint4 vb1 = *(const uint4*)(Bg + (size_t)lr * D_DIM + lq1 * 8);
        *(uint4*)&sA[0][lr * DB_STRIDE + lq0 * 8] = va0;
        *(uint4*)&sA[0][lr * DB_STRIDE + lq1 * 8] = va1;
        *(uint4*)&sB[0][lr * DB_STRIDE + lq0 * 8] = vb0;
        *(uint4*)&sB[0][lr * DB_STRIDE + lq1 * 8] = vb1;
    }
    __syncthreads();

    const int KIT = D_DIM / 32;   // 16
    for (int it = 0; it < KIT; it++) {
        int cur = it & 1;

        // prefetch next chunk to registers
        uint4 pa0, pa1, pb0, pb1;
        if (it + 1 < KIT) {
            int kt = (it + 1) * 32;
            pa0 = *(const uint4*)(Ag + (size_t)lr * D_DIM + kt + lq0 * 8);
            pa1 = *(const uint4*)(Ag + (size_t)lr * D_DIM + kt + lq1 * 8);
            pb0 = *(const uint4*)(Bg + (size_t)lr * D_DIM + kt + lq0 * 8);
            pb1 = *(const uint4*)(Bg + (size_t)lr * D_DIM + kt + lq1 * 8);
        }

        // compute from smem[cur]: 2 k16-steps
        #pragma unroll
        for (int ks = 0; ks < 2; ks++) {
            uint32_t af[4][4], bf[4][2];
            // A fragments: ldmatrix.x4 quadrant addressing
            int arow = (lane & 7) + 8 * ((lane >> 3) & 1);
            int acol = ks * 32 + 16 * (lane >> 4);
            #pragma unroll
            for (int i = 0; i < 4; i++) {
                int row = warp_m * 64 + i * 16 + arow;
                ldmatrix_x4(af[i], a_s[cur] + (uint32_t)(row * 80 + acol));
            }
            // B fragments: ldmatrix.x2
            int brow = lane & 7;
            int bcol = ks * 32 + 16 * ((lane >> 3) & 1);
            #pragma unroll
            for (int j = 0; j < 4; j++) {
                int row = warp_n * 32 + j * 8 + brow;
                ldmatrix_x2(bf[j], b_s[cur] + (uint32_t)(row * 80 + bcol));
            }
            #pragma unroll
            for (int i = 0; i < 4; i++)
                #pragma unroll
                for (int j = 0; j < 4; j++)
                    mma_bf16(acc[i][j], af[i], bf[j]);
        }

        if (it + 1 < KIT) {
            int nxt = cur ^ 1;
            __syncthreads();
            *(uint4*)&sA[nxt][lr * DB_STRIDE + lq0 * 8] = pa0;
            *(uint4*)&sA[nxt][lr * DB_STRIDE + lq1 * 8] = pa1;
            *(uint4*)&sB[nxt][lr * DB_STRIDE + lq0 * 8] = pb0;
            *(uint4*)&sB[nxt][lr * DB_STRIDE + lq1 * 8] = pb1;
            __syncthreads();
        }
    }

    // epilogue: m16n8 C fragment mapping
    int row0 = by * 128 + warp_m * 64;
    int col0 = bx * 128 + warp_n * 32;
    #pragma unroll
    for (int i = 0; i < 4; i++) {
        int ra = row0 + i * 16 + (lane >> 2);
        #pragma unroll
        for (int j = 0; j < 4; j++) {
            int ca = col0 + j * 8 + (lane & 3) * 2;
            *(float2*)(C + (size_t)ra * M_ANC + ca) =
                make_float2(acc[i][j][0], acc[i][j][1]);
            *(float2*)(C + (size_t)(ra + 8) * M_ANC + ca) =
                make_float2(acc[i][j][2], acc[i][j][3]);
        }
    }
}

// ---------------------------------------------------------------------------
// anchor squared norms: one warp per row
// ---------------------------------------------------------------------------
__global__ void anorm_kernel(const float* __restrict__ anchor, float* __restrict__ anorm) {
    int gw = (blockIdx.x * blockDim.x + threadIdx.x) >> 5;
    int lane = threadIdx.x & 31;
    if (gw >= M_ANC) return;
    const float* row = anchor + (size_t)gw * D_DIM;
    float s = 0.f;
    #pragma unroll
    for (int j = lane; j < D_DIM; j += 32) { float v = row[j]; s += v * v; }
    #pragma unroll
    for (int off = 16; off; off >>= 1) s += __shfl_xor_sync(0xffffffffu, s, off);
    if (lane == 0) anorm[gw] = s;
}

// ---------------------------------------------------------------------------
// top-5 with bf16->fp32 refinement. One warp per row.
// ---------------------------------------------------------------------------
#define TK_MARGIN 2.5f
#define TK_MAXC   64

__global__ void __launch_bounds__(256) topk_refine_kernel(
    const float* __restrict__ dots,
    const float* __restrict__ anorm,
    const float* __restrict__ src,
    const float* __restrict__ anchor,
    int* __restrict__ idx_out)
{
    __shared__ int   s_cand[8][TK_MAXC];
    __shared__ float s_dval[8][TK_MAXC];

    int w = threadIdx.x >> 5;
    int row = (blockIdx.x * blockDim.x + threadIdx.x) >> 5;
    int lane = threadIdx.x & 31;
    if (row >= N_SRC) return;

    const float* drow = dots + (size_t)row * M_ANC;

    // ---- pass 1: lane-local approx top-5, merged 5th value ----
    float best[KNN_K];
    int   bidx[KNN_K];
    #pragma unroll
    for (int i = 0; i < KNN_K; i++) { best[i] = FLT_MAX; bidx[i] = 0x7fffffff; }

    for (int m = lane; m < M_ANC; m += 32) {
        float d = anorm[m] - 2.f * drow[m];
        if (d < best[KNN_K - 1]) {
            int p = KNN_K - 1;
            #pragma unroll
            for (int q = KNN_K - 1; q > 0; q--) {
                if (d < best[q - 1]) { best[q] = best[q - 1]; bidx[q] = bidx[q - 1]; p = q - 1; }
            }
            best[p] = d; bidx[p] = m;
        }
    }

    float t5 = FLT_MAX;
    int head = 0;
    #pragma unroll
    for (int s = 0; s < KNN_K; s++) {
        float mv = (head < KNN_K) ? best[head] : FLT_MAX;
        int   mi = (head < KNN_K) ? bidx[head] : 0x7fffffff;
        #pragma unroll
        for (int off = 16; off; off >>= 1) {
            float ov = __shfl_xor_sync(0xffffffffu, mv, off);
            int   oi = __shfl_xor_sync(0xffffffffu, mi, off);
            if (ov < mv || (ov == mv && oi < mi)) { mv = ov; mi = oi; }
        }
        if (head < KNN_K && bidx[head] == mi) head++;
        t5 = mv;
    }
    float thresh = t5 + TK_MARGIN;

    // ---- pass 2: collect candidates ----
    int cnt = 0;
    for (int m = lane; m < M_ANC; m += 32) {
        float d = anorm[m] - 2.f * drow[m];
        bool pred = (d <= thresh);
        unsigned mask = __ballot_sync(0xffffffffu, pred);
        if (pred) {
            int pos = cnt + __popc(mask & ((1u << lane) - 1u));
            if (pos < TK_MAXC) s_cand[w][pos] = m;
        }
        cnt += __popc(mask);
    }
    if (cnt > TK_MAXC) cnt = TK_MAXC;
    __syncwarp();

    // ---- pass 3: exact fp32 distances ----
    float sreg[D_DIM / 32];
    const float* srow = src + (size_t)row * D_DIM;
    #pragma unroll
    for (int j = 0; j < D_DIM / 32; j++) sreg[j] = srow[lane + 32 * j];

    for (int c = 0; c < cnt; c++) {
        int m = s_cand[w][c];
        const float* arow = anchor + (size_t)m * D_DIM;
        float s = 0.f;
        #pragma unroll
        for (int j = 0; j < D_DIM / 32; j++) s += sreg[j] * arow[lane + 32 * j];
        #pragma unroll
        for (int off = 16; off; off >>= 1) s += __shfl_xor_sync(0xffffffffu, s, off);
        if (lane == 0) s_dval[w][c] = anorm[m] - 2.f * s;
    }
    __syncwarp();

    // ---- final exact (value, idx) top-5 ----
    if (lane == 0) {
        #pragma unroll
        for (int s = 0; s < KNN_K; s++) {
            float mv = FLT_MAX; int mi = 0x7fffffff; int mc = -1;
            for (int c = 0; c < cnt; c++) {
                float v = s_dval[w][c]; int id = s_cand[w][c];
                if (v < mv || (v == mv && id < mi)) { mv = v; mi = id; mc = c; }
            }
            idx_out[row * KNN_K + s] = mi;
            if (mc >= 0) s_dval[w][mc] = FLT_MAX;
        }
    }
}

// ---------------------------------------------------------------------------
// Generic fp32 SGEMM: C[M,N] = A[M,K] * B (+bias) (+C) (tanh)
// ---------------------------------------------------------------------------
#define BM 128
#define BN 128
#define BKK 16

template<bool TB, bool ACC, bool BIAS, bool TANH>
__global__ void __launch_bounds__(256, 2) gemm_kernel(
    const float* __restrict__ A, const float* __restrict__ B,
    const float* __restrict__ bias, float* __restrict__ C,
    int M, int N, int K)
{
    __shared__ float As[BKK][BM + 4];
    __shared__ float Bs[BKK][BN + 4];

    int tid = threadIdx.x;
    int bx = blockIdx.x;
    int by = blockIdx.y;

    const float* Ablk = A + (size_t)by * BM * K;
    const float* Bblk = TB ? (B + (size_t)bx * BN * K) : B;

    float acc[8][8];
    #pragma unroll
    for (int i = 0; i < 8; i++)
        #pragma unroll
        for (int j = 0; j < 8; j++) acc[i][j] = 0.f;

    int ar = tid >> 2;
    int ac = (tid & 3) << 2;
    int kb = tid >> 5;
    int nb = (tid & 31) << 2;

    int ty = tid >> 4, tx = tid & 15;

    for (int kt = 0; kt < K; kt += BKK) {
        #pragma unroll
        for (int i = 0; i < 2; i++) {
            int r = ar + i * 64;
            float4 v = *(const float4*)(Ablk + (size_t)r * K + kt + ac);
            As[ac + 0][r] = v.x; As[ac + 1][r] = v.y;
            As[ac + 2][r] = v.z; As[ac + 3][r] = v.w;
        }
        if (TB) {
            #pragma unroll
            for (int i = 0; i < 2; i++) {
                int r = ar + i * 64;
                float4 v = *(const float4*)(Bblk + (size_t)r * K + kt + ac);
                Bs[ac + 0][r] = v.x; Bs[ac + 1][r] = v.y;
                Bs[ac + 2][r] = v.z; Bs[ac + 3][r] = v.w;
            }
        } else {
            #pragma unroll
            for (int i = 0; i < 2; i++) {
                int kk = kb + i * 8;
                float4 v = *(const float4*)(B + (size_t)(kt + kk) * N + bx * BN + nb);
                *(float4*)&Bs[kk][nb] = v;
            }
        }
        __syncthreads();

        #pragma unroll
        for (int k = 0; k < BKK; k++) {
            float a[8], b[8];
            *(float4*)(a)     = *(float4*)&As[k][ty * 8];
            *(float4*)(a + 4) = *(float4*)&As[k][ty * 8 + 4];
            *(float4*)(b)     = *(float4*)&Bs[k][tx * 8];
            *(float4*)(b + 4) = *(float4*)&Bs[k][tx * 8 + 4];
            #pragma unroll
            for (int i = 0; i < 8; i++)
                #pragma unroll
                for (int j = 0; j < 8; j++)
                    acc[i][j] += a[i] * b[j];
        }
        __syncthreads();
    }

    int row0 = by * BM + ty * 8;
    int col0 = bx * BN + tx * 8;
    float bv[8];
    #pragma unroll
    for (int j = 0; j < 8; j++) bv[j] = BIAS ? bias[col0 + j] : 0.f;

    #pragma unroll
    for (int i = 0; i < 8; i++) {
        float* crow = C + (size_t)(row0 + i) * N + col0;
        #pragma unroll
        for (int jj = 0; jj < 2; jj++) {
            float4 old;
            if (ACC) old = *(float4*)(crow + jj * 4);
            float v0 = acc[i][jj * 4 + 0] + bv[jj * 4 + 0];
            float v1 = acc[i][jj * 4 + 1] + bv[jj * 4 + 1];
            float v2 = acc[i][jj * 4 + 2] + bv[jj * 4 + 2];
            float v3 = acc[i][jj * 4 + 3] + bv[jj * 4 + 3];
            if (ACC) { v0 += old.x; v1 += old.y; v2 += old.z; v3 += old.w; }
            if (TANH) { v0 = tanhf(v0); v1 = tanhf(v1); v2 = tanhf(v2); v3 = tanhf(v3); }
            *(float4*)(crow + jj * 4) = make_float4(v0, v1, v2, v3);
        }
    }
}

// ---------------------------------------------------------------------------
// neigh[n,:] = mean of 5 gathered anchor rows.
// ---------------------------------------------------------------------------
__global__ void gather_mean_kernel(const float* __restrict__ anchor,
                                   const int* __restrict__ idx,
                                   float* __restrict__ neigh)
{
    int i = blockIdx.x * blockDim.x + threadIdx.x;
    if (i >= N_SRC * (D_DIM / 4)) return;
    int n = i / (D_DIM / 4);
    int d4 = (i % (D_DIM / 4)) * 4;
    const int* ix = idx + n * KNN_K;
    float4 a = make_float4(0.f, 0.f, 0.f, 0.f);
    #pragma unroll
    for (int k = 0; k < KNN_K; k++) {
        float4 v = *(const float4*)(anchor + (size_t)ix[k] * D_DIM + d4);
        a.x += v.x; a.y += v.y; a.z += v.z; a.w += v.w;
    }
    const float inv = 1.f / (float)KNN_K;
    a.x *= inv; a.y *= inv; a.z *= inv; a.w *= inv;
    *(float4*)(neigh + (size_t)n * D_DIM + d4) = a;
}

// ---------------------------------------------------------------------------
// BatchNorm: deterministic 2-stage column reduction
// ---------------------------------------------------------------------------
__global__ void bn_stats_kernel(const float* __restrict__ X,
                                float* __restrict__ ps, float* __restrict__ qs)
{
    int c = threadIdx.x;
    int r0 = blockIdx.x * 128;
    float s = 0.f, q = 0.f;
    #pragma unroll 4
    for (int r = 0; r < 128; r++) {
        float v = X[(size_t)(r0 + r) * D_DIM + c];
        s += v; q += v * v;
    }
    ps[blockIdx.x * D_DIM + c] = s;
    qs[blockIdx.x * D_DIM + c] = q;
}

__global__ void bn_final_kernel(const float* __restrict__ ps, const float* __restrict__ qs,
                                float* __restrict__ mean, float* __restrict__ rstd)
{
    int c = threadIdx.x;
    float s = 0.f, q = 0.f;
    #pragma unroll 8
    for (int b = 0; b < 128; b++) { s += ps[b * D_DIM + c]; q += qs[b * D_DIM + c]; }
    float m = s * (1.f / (float)N_SRC);
    float v = q * (1.f / (float)N_SRC) - m * m;
    mean[c] = m;
    rstd[c] = rsqrtf(v + BN_EPS);
}

template<bool TANH>
__global__ void bn_apply_kernel(const float* __restrict__ X, float* __restrict__ Y,
                                const float* __restrict__ mean, const float* __restrict__ rstd,
                                const float* __restrict__ g, const float* __restrict__ b)
{
    int i = blockIdx.x * blockDim.x + threadIdx.x;
    if (i >= N_SRC * (D_DIM / 4)) return;
    int c0 = (i * 4) & (D_DIM - 1);
    float4 x = *(const float4*)(X + (size_t)i * 4);
    float v0 = (x.x - mean[c0 + 0]) * rstd[c0 + 0] * g[c0 + 0] + b[c0 + 0];
    float v1 = (x.y - mean[c0 + 1]) * rstd[c0 + 1] * g[c0 + 1] + b[c0 + 1];
    float v2 = (x.z - mean[c0 + 2]) * rstd[c0 + 2] * g[c0 + 2] + b[c0 + 2];
    float v3 = (x.w - mean[c0 + 3]) * rstd[c0 + 3] * g[c0 + 3] + b[c0 + 3];
    if (TANH) { v0 = tanhf(v0); v1 = tanhf(v1); v2 = tanhf(v2); v3 = tanhf(v3); }
    *(float4*)(Y + (size_t)i * 4) = make_float4(v0, v1, v2, v3);
}

__global__ void add_kernel(float* __restrict__ A, const float* __restrict__ B, int n4)
{
    int i = blockIdx.x * blockDim.x + threadIdx.x;
    if (i >= n4) return;
    float4 a = *(float4*)(A + (size_t)i * 4);
    float4 b = *(const float4*)(B + (size_t)i * 4);
    a.x += b.x; a.y += b.y; a.z += b.z; a.w += b.w;
    *(float4*)(A + (size_t)i * 4) = a;
}

// ---------------------------------------------------------------------------
// launch
// ---------------------------------------------------------------------------
extern "C" void kernel_launch(void* const* d_in, const int* in_sizes, int n_in,
                              void* d_out, int out_size)
{
    const float* src    = (const float*)d_in[0];
    const float* anchor = (const float*)d_in[1];
    const float* W_dim  = (const float*)d_in[2];
    const float* b_dim  = (const float*)d_in[3];
    const float* W_fus  = (const float*)d_in[4];
    const float* b_fus  = (const float*)d_in[5];
    const float* W_e1   = (const float*)d_in[6];
    const float* b_e1   = (const float*)d_in[7];
    const float* W_e2   = (const float*)d_in[8];
    const float* b_e2   = (const float*)d_in[9];
    const float* g1     = (const float*)d_in[10];
    const float* bt1    = (const float*)d_in[11];
    const float* g2     = (const float*)d_in[12];
    const float* bt2    = (const float*)d_in[13];
    const float* W_d    = (const float*)d_in[14];
    const float* b_d    = (const float*)d_in[15];
    const float* g_d    = (const float*)d_in[16];
    const float* bt_d   = (const float*)d_in[17];
    float* out = (float*)d_out;

    float *dots, *anorm, *neigh, *amap, *comb, *hidden, *tbuf, *zbuf;
    float *ps, *qs, *mean, *rstd;
    int* idx;
    __nv_bfloat16 *src_bf, *anc_bf;
    cudaGetSymbolAddress((void**)&dots,   g_dots);
    cudaGetSymbolAddress((void**)&anorm,  g_anorm);
    cudaGetSymbolAddress((void**)&idx,    g_idx);
    cudaGetSymbolAddress((void**)&neigh,  g_neigh);
    cudaGetSymbolAddress((void**)&amap,   g_amap);
    cudaGetSymbolAddress((void**)&comb,   g_comb);
    cudaGetSymbolAddress((void**)&hidden, g_hidden);
    cudaGetSymbolAddress((void**)&tbuf,   g_tbuf);
    cudaGetSymbolAddress((void**)&zbuf,   g_zbuf);
    cudaGetSymbolAddress((void**)&ps,     g_ps);
    cudaGetSymbolAddress((void**)&qs,     g_qs);
    cudaGetSymbolAddress((void**)&mean,   g_mean);
    cudaGetSymbolAddress((void**)&rstd,   g_rstd);
    cudaGetSymbolAddress((void**)&src_bf, g_src_bf);
    cudaGetSymbolAddress((void**)&anc_bf, g_anc_bf);

    const int ND4 = N_SRC * (D_DIM / 4);

    // 0. bf16 conversions
    tobf16_kernel<<<(N_SRC * D_DIM / 4 + 255) / 256, 256>>>(src, src_bf, N_SRC * D_DIM / 4);
    tobf16_kernel<<<(M_ANC * D_DIM / 4 + 255) / 256, 256>>>(anchor, anc_bf, M_ANC * D_DIM / 4);

    // 1. anchor norms (fp32 exact)
    anorm_kernel<<<(M_ANC * 32 + 255) / 256, 256>>>(anchor, anorm);

    // 2. dots = src @ anchor^T on tensor cores (bf16 ldmatrix + mma)
    dist_gemm_bf16_kernel<<<dim3(M_ANC / 128, N_SRC / 128), 256>>>(src_bf, anc_bf, dots);

    // 3. top-5 per row with fp32 refinement
    topk_refine_kernel<<<(N_SRC * 32) / 256, 256>>>(dots, anorm, src, anchor, idx);

    // 4. gather + mean
    gather_mean_kernel<<<(ND4 + 255) / 256, 256>>>(anchor, idx, neigh);

    // 5. a_map = neigh @ W_dim + b_dim
    gemm_kernel<false, false, true, false><<<dim3(D_DIM / BN, N_SRC / BM), 256>>>(
        neigh, W_dim, b_dim, amap, N_SRC, D_DIM, D_DIM);

    // 6. comb = src @ W_fus[:512] + b_fus ; += a_map @ W_fus[512:]
    gemm_kernel<false, false, true, false><<<dim3(D_DIM / BN, N_SRC / BM), 256>>>(
        src, W_fus, b_fus, comb, N_SRC, D_DIM, D_DIM);
    gemm_kernel<false, true, false, false><<<dim3(D_DIM / BN, N_SRC / BM), 256>>>(
        amap, W_fus + (size_t)D_DIM * D_DIM, nullptr, comb, N_SRC, D_DIM, D_DIM);

    // 7. BN1 (in place)
    bn_stats_kernel<<<128, 512>>>(comb, ps, qs);
    bn_final_kernel<<<1, 512>>>(ps, qs, mean, rstd);
    bn_apply_kernel<false><<<(ND4 + 255) / 256, 256>>>(comb, comb, mean, rstd, g1, bt1);

    // 8. hidden = tanh(comb @ W_e1 + b_e1)
    gemm_kernel<false, false, true, true><<<dim3(F_DIM / BN, N_SRC / BM), 256>>>(
        comb, W_e1, b_e1, hidden, N_SRC, F_DIM, D_DIM);

    // 9. tbuf = hidden @ W_e2 + b_e2
    gemm_kernel<false, false, true, false><<<dim3(D_DIM / BN, N_SRC / BM), 256>>>(
        hidden, W_e2, b_e2, tbuf, N_SRC, D_DIM, F_DIM);

    // 10. comb += tbuf ; BN2 in place
    add_kernel<<<(ND4 + 255) / 256, 256>>>(comb, tbuf, ND4);
    bn_stats_kernel<<<128, 512>>>(comb, ps, qs);
    bn_final_kernel<<<1, 512>>>(ps, qs, mean, rstd);
    bn_apply_kernel<false><<<(ND4 + 255) / 256, 256>>>(comb, comb, mean, rstd, g2, bt2);

    // 11. zbuf = comb @ W_d + b_d ; out = tanh(BN(zbuf))
    gemm_kernel<false, false, true, false><<<dim3(D_DIM / BN, N_SRC / BM), 256>>>(
        comb, W_d, b_d, zbuf, N_SRC, D_DIM, D_DIM);
    bn_stats_kernel<<<128, 512>>>(zbuf, ps, qs);
    bn_final_kernel<<<1, 512>>>(ps, qs, mean, rstd);
    bn_apply_kernel<true><<<(ND4 + 255) / 256, 256>>>(zbuf, out, mean, rstd, g_d, bt_d);
}

// round 9
// speedup vs baseline: 2.1256x; 1.3750x over previous
#include <cuda_runtime.h>
#include <cuda_bf16.h>
#include <math.h>
#include <float.h>
#include <stdint.h>

// Problem constants
#define N_SRC   16384
#define M_ANC   8192
#define D_DIM   512
#define F_DIM   2048
#define KNN_K   5
#define BN_EPS  1e-5f

// ---------------------------------------------------------------------------
// Scratch (static device allocations; no cudaMalloc allowed)
// ---------------------------------------------------------------------------
__device__ float g_dots[(size_t)N_SRC * M_ANC];     // 512 MB
__device__ float g_anorm[M_ANC];
__device__ int   g_idx[N_SRC * KNN_K];
__device__ float g_comb[(size_t)N_SRC * D_DIM];
__device__ float g_tbuf[(size_t)N_SRC * D_DIM];
__device__ float g_zbuf[(size_t)N_SRC * D_DIM];
__device__ float g_ps[128 * D_DIM];
__device__ float g_qs[128 * D_DIM];
__device__ float g_mean[D_DIM];
__device__ float g_rstd[D_DIM];
__device__ __nv_bfloat16 g_src_bf[(size_t)N_SRC * D_DIM];
__device__ __nv_bfloat16 g_anc_bf[(size_t)M_ANC * D_DIM];
// split operands
__device__ __nv_bfloat16 g_catA_hi[(size_t)N_SRC * 1024];   // [src | amap]
__device__ __nv_bfloat16 g_catA_lo[(size_t)N_SRC * 1024];
__device__ __nv_bfloat16 g_neigh_hi[(size_t)N_SRC * D_DIM];
__device__ __nv_bfloat16 g_neigh_lo[(size_t)N_SRC * D_DIM];
__device__ __nv_bfloat16 g_comb_hi[(size_t)N_SRC * D_DIM];
__device__ __nv_bfloat16 g_comb_lo[(size_t)N_SRC * D_DIM];
__device__ __nv_bfloat16 g_hid_hi[(size_t)N_SRC * F_DIM];
__device__ __nv_bfloat16 g_hid_lo[(size_t)N_SRC * F_DIM];
// transposed + split weights [N, K]
__device__ __nv_bfloat16 g_WdimT_hi[512 * 512],  g_WdimT_lo[512 * 512];
__device__ __nv_bfloat16 g_WfusT_hi[512 * 1024], g_WfusT_lo[512 * 1024];
__device__ __nv_bfloat16 g_We1T_hi[2048 * 512],  g_We1T_lo[2048 * 512];
__device__ __nv_bfloat16 g_We2T_hi[512 * 2048],  g_We2T_lo[512 * 2048];
__device__ __nv_bfloat16 g_WdT_hi[512 * 512],    g_WdT_lo[512 * 512];

// ---------------------------------------------------------------------------
// small helpers
// ---------------------------------------------------------------------------
__device__ __forceinline__ void split2(float v0, float v1,
                                       __nv_bfloat162& hi, __nv_bfloat162& lo)
{
    hi = __floats2bfloat162_rn(v0, v1);
    lo = __floats2bfloat162_rn(v0 - __bfloat162float(hi.x),
                               v1 - __bfloat162float(hi.y));
}

__device__ __forceinline__ void cp_async16(uint32_t saddr, const void* gaddr)
{
    asm volatile("cp.async.cg.shared.global [%0], [%1], 16;\n"
                 :: "r"(saddr), "l"(gaddr));
}
#define CP_COMMIT() asm volatile("cp.async.commit_group;\n" ::: "memory")
#define CP_WAIT0()  asm volatile("cp.async.wait_group 0;\n" ::: "memory")

__device__ __forceinline__ void mma_bf16(float* c, const uint32_t* a, const uint32_t* b)
{
    asm volatile(
        "mma.sync.aligned.m16n8k16.row.col.f32.bf16.bf16.f32 "
        "{%0,%1,%2,%3}, {%4,%5,%6,%7}, {%8,%9}, {%0,%1,%2,%3};"
        : "+f"(c[0]), "+f"(c[1]), "+f"(c[2]), "+f"(c[3])
        : "r"(a[0]), "r"(a[1]), "r"(a[2]), "r"(a[3]),
          "r"(b[0]), "r"(b[1]));
}

__device__ __forceinline__ void ldmatrix_x4(uint32_t* r, uint32_t saddr)
{
    asm volatile("ldmatrix.sync.aligned.m8n8.x4.shared.b16 {%0,%1,%2,%3}, [%4];"
                 : "=r"(r[0]), "=r"(r[1]), "=r"(r[2]), "=r"(r[3]) : "r"(saddr));
}
__device__ __forceinline__ void ldmatrix_x2(uint32_t* r, uint32_t saddr)
{
    asm volatile("ldmatrix.sync.aligned.m8n8.x2.shared.b16 {%0,%1}, [%2];"
                 : "=r"(r[0]), "=r"(r[1]) : "r"(saddr));
}

// ---------------------------------------------------------------------------
// conversions
// ---------------------------------------------------------------------------
__global__ void tobf16_kernel(const float* __restrict__ x,
                              __nv_bfloat16* __restrict__ y, int n4)
{
    int i = blockIdx.x * blockDim.x + threadIdx.x;
    if (i >= n4) return;
    float4 v = *(const float4*)(x + (size_t)i * 4);
    __nv_bfloat162* o = (__nv_bfloat162*)(y + (size_t)i * 4);
    o[0] = __floats2bfloat162_rn(v.x, v.y);
    o[1] = __floats2bfloat162_rn(v.z, v.w);
}

// src [N,512] fp32 -> catA hi/lo cols [0,512) of a [N,1024] buffer
__global__ void split_src_kernel(const float* __restrict__ x,
                                 __nv_bfloat16* __restrict__ yh,
                                 __nv_bfloat16* __restrict__ yl)
{
    int i = blockIdx.x * blockDim.x + threadIdx.x;     // over N*128
    if (i >= N_SRC * (D_DIM / 4)) return;
    int n = i >> 7;
    int c = (i & 127) * 4;
    float4 v = *(const float4*)(x + (size_t)n * D_DIM + c);
    __nv_bfloat162 h0, l0, h1, l1;
    split2(v.x, v.y, h0, l0);
    split2(v.z, v.w, h1, l1);
    size_t o = (size_t)n * 1024 + c;
    *(__nv_bfloat162*)(yh + o)     = h0;
    *(__nv_bfloat162*)(yh + o + 2) = h1;
    *(__nv_bfloat162*)(yl + o)     = l0;
    *(__nv_bfloat162*)(yl + o + 2) = l1;
}

// W [K,N] fp32 -> T_hi/T_lo [N,K] bf16
__global__ void transpose_split_kernel(const float* __restrict__ W,
                                       __nv_bfloat16* __restrict__ Th,
                                       __nv_bfloat16* __restrict__ Tl,
                                       int K, int N)
{
    __shared__ float t[32][33];
    int n0 = blockIdx.x * 32, k0 = blockIdx.y * 32;
    int tx = threadIdx.x, ty = threadIdx.y;    // 32 x 8
    #pragma unroll
    for (int r = 0; r < 4; r++)
        t[ty + r * 8][tx] = W[(size_t)(k0 + ty + r * 8) * N + n0 + tx];
    __syncthreads();
    #pragma unroll
    for (int r = 0; r < 4; r++) {
        float v = t[tx][ty + r * 8];
        __nv_bfloat16 h = __float2bfloat16(v);
        Th[(size_t)(n0 + ty + r * 8) * K + k0 + tx] = h;
        Tl[(size_t)(n0 + ty + r * 8) * K + k0 + tx] =
            __float2bfloat16(v - __bfloat162float(h));
    }
}

// ===========================================================================
// Split-bf16 GEMM: C[M,N] = (Ahi+Alo)[M,K] @ (Bhi+Blo)[N,K]^T + bias
// 3-term MMA (hi*hi + hi*lo + lo*hi), fp32 accum. CTA 128x128, BK=32,
// cp.async double buffer (80KB dynamic smem).
// ===========================================================================
#define GS_TILE_B 10240          // 128 rows * 80 bytes

// loader: 16 cp.async per thread-group invocation (manually unrolled)
__device__ __forceinline__ void gs_load_chunk(
    uint32_t sbase, int buf,
    const __nv_bfloat16* gAh, const __nv_bfloat16* gAl,
    const __nv_bfloat16* gBh, const __nv_bfloat16* gBl,
    int lr, int lq0, int kt, int K)
{
    uint32_t b = sbase + (uint32_t)buf * (4 * GS_TILE_B);
    int lq1 = lq0 + 2;
    const __nv_bfloat16* ah = gAh + (size_t)lr * K + kt;
    const __nv_bfloat16* al = gAl + (size_t)lr * K + kt;
    const __nv_bfloat16* bh = gBh + (size_t)lr * K + kt;
    const __nv_bfloat16* bl = gBl + (size_t)lr * K + kt;
    uint32_t ro = (uint32_t)(lr * 80);
    cp_async16(b + 0 * GS_TILE_B + ro + lq0 * 16, ah + lq0 * 8);
    cp_async16(b + 0 * GS_TILE_B + ro + lq1 * 16, ah + lq1 * 8);
    cp_async16(b + 1 * GS_TILE_B + ro + lq0 * 16, al + lq0 * 8);
    cp_async16(b + 1 * GS_TILE_B + ro + lq1 * 16, al + lq1 * 8);
    cp_async16(b + 2 * GS_TILE_B + ro + lq0 * 16, bh + lq0 * 8);
    cp_async16(b + 2 * GS_TILE_B + ro + lq1 * 16, bh + lq1 * 8);
    cp_async16(b + 3 * GS_TILE_B + ro + lq0 * 16, bl + lq0 * 8);
    cp_async16(b + 3 * GS_TILE_B + ro + lq1 * 16, bl + lq1 * 8);
}

template<bool TANH, bool OUT32, bool OUTSPLIT>
__global__ void __launch_bounds__(256) gemm_split_kernel(
    const __nv_bfloat16* __restrict__ Ahi, const __nv_bfloat16* __restrict__ Alo,
    const __nv_bfloat16* __restrict__ Bhi, const __nv_bfloat16* __restrict__ Blo,
    const float* __restrict__ bias,
    float* __restrict__ C32,
    __nv_bfloat16* __restrict__ Chi, __nv_bfloat16* __restrict__ Clo,
    int ldC, int N, int K)
{
    extern __shared__ __nv_bfloat16 smem[];
    uint32_t sb = (uint32_t)__cvta_generic_to_shared(smem);

    int tid = threadIdx.x;
    int lane = tid & 31;
    int wid = tid >> 5;
    int warp_m = wid >> 2;
    int warp_n = wid & 3;
    int bx = blockIdx.x;
    int by = blockIdx.y;

    const __nv_bfloat16* gAh = Ahi + (size_t)(by * 128) * K;
    const __nv_bfloat16* gAl = Alo + (size_t)(by * 128) * K;
    const __nv_bfloat16* gBh = Bhi + (size_t)(bx * 128) * K;
    const __nv_bfloat16* gBl = Blo + (size_t)(bx * 128) * K;

    float acc[4][4][4];
    #pragma unroll
    for (int i = 0; i < 4; i++)
        #pragma unroll
        for (int j = 0; j < 4; j++)
            #pragma unroll
            for (int e = 0; e < 4; e++) acc[i][j][e] = 0.f;

    int lr = tid & 127;
    int lq0 = tid >> 7;     // 0/1; quarters {lq0, lq0+2}

    gs_load_chunk(sb, 0, gAh, gAl, gBh, gBl, lr, lq0, 0, K);
    CP_COMMIT();
    CP_WAIT0();
    __syncthreads();

    const int KIT = K / 32;
    for (int it = 0; it < KIT; it++) {
        int cur = it & 1;
        if (it + 1 < KIT) {
            gs_load_chunk(sb, cur ^ 1, gAh, gAl, gBh, gBl, lr, lq0, (it + 1) * 32, K);
            CP_COMMIT();
        }

        uint32_t tAh = sb + (uint32_t)cur * (4 * GS_TILE_B);
        uint32_t tAl = tAh + GS_TILE_B;
        uint32_t tBh = tAh + 2 * GS_TILE_B;
        uint32_t tBl = tAh + 3 * GS_TILE_B;

        #pragma unroll
        for (int ks = 0; ks < 2; ks++) {
            uint32_t afh[4][4], afl[4][4], bfh[4][2], bfl[4][2];
            int arow = (lane & 7) + 8 * ((lane >> 3) & 1);
            int acol = ks * 32 + 16 * (lane >> 4);
            #pragma unroll
            for (int i = 0; i < 4; i++) {
                int row = warp_m * 64 + i * 16 + arow;
                ldmatrix_x4(afh[i], tAh + (uint32_t)(row * 80 + acol));
                ldmatrix_x4(afl[i], tAl + (uint32_t)(row * 80 + acol));
            }
            int brow = lane & 7;
            int bcol = ks * 32 + 16 * ((lane >> 3) & 1);
            #pragma unroll
            for (int j = 0; j < 4; j++) {
                int row = warp_n * 32 + j * 8 + brow;
                ldmatrix_x2(bfh[j], tBh + (uint32_t)(row * 80 + bcol));
                ldmatrix_x2(bfl[j], tBl + (uint32_t)(row * 80 + bcol));
            }
            #pragma unroll
            for (int i = 0; i < 4; i++)
                #pragma unroll
                for (int j = 0; j < 4; j++) {
                    mma_bf16(acc[i][j], afh[i], bfh[j]);
                    mma_bf16(acc[i][j], afh[i], bfl[j]);
                    mma_bf16(acc[i][j], afl[i], bfh[j]);
                }
        }

        if (it + 1 < KIT) {
            CP_WAIT0();
            __syncthreads();
        }
    }

    // epilogue
    int row0 = by * 128 + warp_m * 64;
    int col0 = bx * 128 + warp_n * 32;
    #pragma unroll
    for (int i = 0; i < 4; i++) {
        int ra = row0 + i * 16 + (lane >> 2);
        #pragma unroll
        for (int j = 0; j < 4; j++) {
            int ca = col0 + j * 8 + (lane & 3) * 2;
            float b0 = bias[ca], b1 = bias[ca + 1];
            float v0 = acc[i][j][0] + b0, v1 = acc[i][j][1] + b1;
            float w0 = acc[i][j][2] + b0, w1 = acc[i][j][3] + b1;
            if (TANH) { v0 = tanhf(v0); v1 = tanhf(v1); w0 = tanhf(w0); w1 = tanhf(w1); }
            if (OUT32) {
                *(float2*)(C32 + (size_t)ra * ldC + ca)       = make_float2(v0, v1);
                *(float2*)(C32 + (size_t)(ra + 8) * ldC + ca) = make_float2(w0, w1);
            }
            if (OUTSPLIT) {
                __nv_bfloat162 h, l;
                split2(v0, v1, h, l);
                *(__nv_bfloat162*)(Chi + (size_t)ra * ldC + ca) = h;
                *(__nv_bfloat162*)(Clo + (size_t)ra * ldC + ca) = l;
                split2(w0, w1, h, l);
                *(__nv_bfloat162*)(Chi + (size_t)(ra + 8) * ldC + ca) = h;
                *(__nv_bfloat162*)(Clo + (size_t)(ra + 8) * ldC + ca) = l;
            }
        }
    }
}

// ===========================================================================
// Distance GEMM (bf16 ldmatrix + mma) -- unchanged from R7
// ===========================================================================
#define DB_STRIDE 40

__global__ void __launch_bounds__(256, 2) dist_gemm_bf16_kernel(
    const __nv_bfloat16* __restrict__ A,
    const __nv_bfloat16* __restrict__ B,
    float* __restrict__ C)
{
    __shared__ __nv_bfloat16 sA[2][128 * DB_STRIDE];
    __shared__ __nv_bfloat16 sB[2][128 * DB_STRIDE];

    int tid = threadIdx.x;
    int lane = tid & 31;
    int wid = tid >> 5;
    int warp_m = wid >> 2;
    int warp_n = wid & 3;
    int bx = blockIdx.x;
    int by = blockIdx.y;

    const __nv_bfloat16* Ag = A + (size_t)(by * 128) * D_DIM;
    const __nv_bfloat16* Bg = B + (size_t)(bx * 128) * D_DIM;

    float acc[4][4][4];
    #pragma unroll
    for (int i = 0; i < 4; i++)
        #pragma unroll
        for (int j = 0; j < 4; j++)
            #pragma unroll
            for (int e = 0; e < 4; e++) acc[i][j][e] = 0.f;

    int lr = tid & 127;
    int lq0 = tid >> 7;
    int lq1 = lq0 + 2;

    uint32_t a_s[2], b_s[2];
    a_s[0] = (uint32_t)__cvta_generic_to_shared(&sA[0][0]);
    a_s[1] = (uint32_t)__cvta_generic_to_shared(&sA[1][0]);
    b_s[0] = (uint32_t)__cvta_generic_to_shared(&sB[0][0]);
    b_s[1] = (uint32_t)__cvta_generic_to_shared(&sB[1][0]);

    {
        uint4 va0 = *(const uint4*)(Ag + (size_t)lr * D_DIM + lq0 * 8);
        uint4 va1 = *(const uint4*)(Ag + (size_t)lr * D_DIM + lq1 * 8);
        uint4 vb0 = *(const uint4*)(Bg + (size_t)lr * D_DIM + lq0 * 8);
        uint4 vb1 = *(const uint4*)(Bg + (size_t)lr * D_DIM + lq1 * 8);
        *(uint4*)&sA[0][lr * DB_STRIDE + lq0 * 8] = va0;
        *(uint4*)&sA[0][lr * DB_STRIDE + lq1 * 8] = va1;
        *(uint4*)&sB[0][lr * DB_STRIDE + lq0 * 8] = vb0;
        *(uint4*)&sB[0][lr * DB_STRIDE + lq1 * 8] = vb1;
    }
    __syncthreads();

    const int KIT = D_DIM / 32;
    for (int it = 0; it < KIT; it++) {
        int cur = it & 1;

        uint4 pa0, pa1, pb0, pb1;
        if (it + 1 < KIT) {
            int kt = (it + 1) * 32;
            pa0 = *(const uint4*)(Ag + (size_t)lr * D_DIM + kt + lq0 * 8);
            pa1 = *(const uint4*)(Ag + (size_t)lr * D_DIM + kt + lq1 * 8);
            pb0 = *(const uint4*)(Bg + (size_t)lr * D_DIM + kt + lq0 * 8);
            pb1 = *(const uint4*)(Bg + (size_t)lr * D_DIM + kt + lq1 * 8);
        }

        #pragma unroll
        for (int ks = 0; ks < 2; ks++) {
            uint32_t af[4][4], bf[4][2];
            int arow = (lane & 7) + 8 * ((lane >> 3) & 1);
            int acol = ks * 32 + 16 * (lane >> 4);
            #pragma unroll
            for (int i = 0; i < 4; i++) {
                int row = warp_m * 64 + i * 16 + arow;
                ldmatrix_x4(af[i], a_s[cur] + (uint32_t)(row * 80 + acol));
            }
            int brow = lane & 7;
            int bcol = ks * 32 + 16 * ((lane >> 3) & 1);
            #pragma unroll
            for (int j = 0; j < 4; j++) {
                int row = warp_n * 32 + j * 8 + brow;
                ldmatrix_x2(bf[j], b_s[cur] + (uint32_t)(row * 80 + bcol));
            }
            #pragma unroll
            for (int i = 0; i < 4; i++)
                #pragma unroll
                for (int j = 0; j < 4; j++)
                    mma_bf16(acc[i][j], af[i], bf[j]);
        }

        if (it + 1 < KIT) {
            int nxt = cur ^ 1;
            __syncthreads();
            *(uint4*)&sA[nxt][lr * DB_STRIDE + lq0 * 8] = pa0;
            *(uint4*)&sA[nxt][lr * DB_STRIDE + lq1 * 8] = pa1;
            *(uint4*)&sB[nxt][lr * DB_STRIDE + lq0 * 8] = pb0;
            *(uint4*)&sB[nxt][lr * DB_STRIDE + lq1 * 8] = pb1;
            __syncthreads();
        }
    }

    int row0 = by * 128 + warp_m * 64;
    int col0 = bx * 128 + warp_n * 32;
    #pragma unroll
    for (int i = 0; i < 4; i++) {
        int ra = row0 + i * 16 + (lane >> 2);
        #pragma unroll
        for (int j = 0; j < 4; j++) {
            int ca = col0 + j * 8 + (lane & 3) * 2;
            *(float2*)(C + (size_t)ra * M_ANC + ca) =
                make_float2(acc[i][j][0], acc[i][j][1]);
            *(float2*)(C + (size_t)(ra + 8) * M_ANC + ca) =
                make_float2(acc[i][j][2], acc[i][j][3]);
        }
    }
}

// ---------------------------------------------------------------------------
// anchor squared norms
// ---------------------------------------------------------------------------
__global__ void anorm_kernel(const float* __restrict__ anchor, float* __restrict__ anorm) {
    int gw = (blockIdx.x * blockDim.x + threadIdx.x) >> 5;
    int lane = threadIdx.x & 31;
    if (gw >= M_ANC) return;
    const float* row = anchor + (size_t)gw * D_DIM;
    float s = 0.f;
    #pragma unroll
    for (int j = lane; j < D_DIM; j += 32) { float v = row[j]; s += v * v; }
    #pragma unroll
    for (int off = 16; off; off >>= 1) s += __shfl_xor_sync(0xffffffffu, s, off);
    if (lane == 0) anorm[gw] = s;
}

// ---------------------------------------------------------------------------
// top-5 with bf16->fp32 refinement (unchanged)
// ---------------------------------------------------------------------------
#define TK_MARGIN 2.5f
#define TK_MAXC   64

__global__ void __launch_bounds__(256) topk_refine_kernel(
    const float* __restrict__ dots,
    const float* __restrict__ anorm,
    const float* __restrict__ src,
    const float* __restrict__ anchor,
    int* __restrict__ idx_out)
{
    __shared__ int   s_cand[8][TK_MAXC];
    __shared__ float s_dval[8][TK_MAXC];

    int w = threadIdx.x >> 5;
    int row = (blockIdx.x * blockDim.x + threadIdx.x) >> 5;
    int lane = threadIdx.x & 31;
    if (row >= N_SRC) return;

    const float* drow = dots + (size_t)row * M_ANC;

    float best[KNN_K];
    int   bidx[KNN_K];
    #pragma unroll
    for (int i = 0; i < KNN_K; i++) { best[i] = FLT_MAX; bidx[i] = 0x7fffffff; }

    for (int m = lane; m < M_ANC; m += 32) {
        float d = anorm[m] - 2.f * drow[m];
        if (d < best[KNN_K - 1]) {
            int p = KNN_K - 1;
            #pragma unroll
            for (int q = KNN_K - 1; q > 0; q--) {
                if (d < best[q - 1]) { best[q] = best[q - 1]; bidx[q] = bidx[q - 1]; p = q - 1; }
            }
            best[p] = d; bidx[p] = m;
        }
    }

    float t5 = FLT_MAX;
    int head = 0;
    #pragma unroll
    for (int s = 0; s < KNN_K; s++) {
        float mv = (head < KNN_K) ? best[head] : FLT_MAX;
        int   mi = (head < KNN_K) ? bidx[head] : 0x7fffffff;
        #pragma unroll
        for (int off = 16; off; off >>= 1) {
            float ov = __shfl_xor_sync(0xffffffffu, mv, off);
            int   oi = __shfl_xor_sync(0xffffffffu, mi, off);
            if (ov < mv || (ov == mv && oi < mi)) { mv = ov; mi = oi; }
        }
        if (head < KNN_K && bidx[head] == mi) head++;
        t5 = mv;
    }
    float thresh = t5 + TK_MARGIN;

    int cnt = 0;
    for (int m = lane; m < M_ANC; m += 32) {
        float d = anorm[m] - 2.f * drow[m];
        bool pred = (d <= thresh);
        unsigned mask = __ballot_sync(0xffffffffu, pred);
        if (pred) {
            int pos = cnt + __popc(mask & ((1u << lane) - 1u));
            if (pos < TK_MAXC) s_cand[w][pos] = m;
        }
        cnt += __popc(mask);
    }
    if (cnt > TK_MAXC) cnt = TK_MAXC;
    __syncwarp();

    float sreg[D_DIM / 32];
    const float* srow = src + (size_t)row * D_DIM;
    #pragma unroll
    for (int j = 0; j < D_DIM / 32; j++) sreg[j] = srow[lane + 32 * j];

    for (int c = 0; c < cnt; c++) {
        int m = s_cand[w][c];
        const float* arow = anchor + (size_t)m * D_DIM;
        float s = 0.f;
        #pragma unroll
        for (int j = 0; j < D_DIM / 32; j++) s += sreg[j] * arow[lane + 32 * j];
        #pragma unroll
        for (int off = 16; off; off >>= 1) s += __shfl_xor_sync(0xffffffffu, s, off);
        if (lane == 0) s_dval[w][c] = anorm[m] - 2.f * s;
    }
    __syncwarp();

    if (lane == 0) {
        #pragma unroll
        for (int s = 0; s < KNN_K; s++) {
            float mv = FLT_MAX; int mi = 0x7fffffff; int mc = -1;
            for (int c = 0; c < cnt; c++) {
                float v = s_dval[w][c]; int id = s_cand[w][c];
                if (v < mv || (v == mv && id < mi)) { mv = v; mi = id; mc = c; }
            }
            idx_out[row * KNN_K + s] = mi;
            if (mc >= 0) s_dval[w][mc] = FLT_MAX;
        }
    }
}

// ---------------------------------------------------------------------------
// gather + mean -> split bf16 output
// ---------------------------------------------------------------------------
__global__ void gather_mean_split_kernel(const float* __restrict__ anchor,
                                         const int* __restrict__ idx,
                                         __nv_bfloat16* __restrict__ yh,
                                         __nv_bfloat16* __restrict__ yl)
{
    int i = blockIdx.x * blockDim.x + threadIdx.x;
    if (i >= N_SRC * (D_DIM / 4)) return;
    int n = i / (D_DIM / 4);
    int d4 = (i % (D_DIM / 4)) * 4;
    const int* ix = idx + n * KNN_K;
    float4 a = make_float4(0.f, 0.f, 0.f, 0.f);
    #pragma unroll
    for (int k = 0; k < KNN_K; k++) {
        float4 v = *(const float4*)(anchor + (size_t)ix[k] * D_DIM + d4);
        a.x += v.x; a.y += v.y; a.z += v.z; a.w += v.w;
    }
    const float inv = 1.f / (float)KNN_K;
    a.x *= inv; a.y *= inv; a.z *= inv; a.w *= inv;
    __nv_bfloat162 h0, l0, h1, l1;
    split2(a.x, a.y, h0, l0);
    split2(a.z, a.w, h1, l1);
    size_t o = (size_t)n * D_DIM + d4;
    *(__nv_bfloat162*)(yh + o)     = h0;
    *(__nv_bfloat162*)(yh + o + 2) = h1;
    *(__nv_bfloat162*)(yl + o)     = l0;
    *(__nv_bfloat162*)(yl + o + 2) = l1;
}

// ---------------------------------------------------------------------------
// BatchNorm
// ---------------------------------------------------------------------------
__global__ void bn_stats_kernel(const float* __restrict__ X,
                                float* __restrict__ ps, float* __restrict__ qs)
{
    int c = threadIdx.x;
    int r0 = blockIdx.x * 128;
    float s = 0.f, q = 0.f;
    #pragma unroll 4
    for (int r = 0; r < 128; r++) {
        float v = X[(size_t)(r0 + r) * D_DIM + c];
        s += v; q += v * v;
    }
    ps[blockIdx.x * D_DIM + c] = s;
    qs[blockIdx.x * D_DIM + c] = q;
}

__global__ void bn_final_kernel(const float* __restrict__ ps, const float* __restrict__ qs,
                                float* __restrict__ mean, float* __restrict__ rstd)
{
    int c = threadIdx.x;
    float s = 0.f, q = 0.f;
    #pragma unroll 8
    for (int b = 0; b < 128; b++) { s += ps[b * D_DIM + c]; q += qs[b * D_DIM + c]; }
    float m = s * (1.f / (float)N_SRC);
    float v = q * (1.f / (float)N_SRC) - m * m;
    mean[c] = m;
    rstd[c] = rsqrtf(v + BN_EPS);
}

template<bool TANH>
__global__ void bn_apply_kernel(const float* __restrict__ X, float* __restrict__ Y,
                                const float* __restrict__ mean, const float* __restrict__ rstd,
                                const float* __restrict__ g, const float* __restrict__ b)
{
    int i = blockIdx.x * blockDim.x + threadIdx.x;
    if (i >= N_SRC * (D_DIM / 4)) return;
    int c0 = (i * 4) & (D_DIM - 1);
    float4 x = *(const float4*)(X + (size_t)i * 4);
    float v0 = (x.x - mean[c0 + 0]) * rstd[c0 + 0] * g[c0 + 0] + b[c0 + 0];
    float v1 = (x.y - mean[c0 + 1]) * rstd[c0 + 1] * g[c0 + 1] + b[c0 + 1];
    float v2 = (x.z - mean[c0 + 2]) * rstd[c0 + 2] * g[c0 + 2] + b[c0 + 2];
    float v3 = (x.w - mean[c0 + 3]) * rstd[c0 + 3] * g[c0 + 3] + b[c0 + 3];
    if (TANH) { v0 = tanhf(v0); v1 = tanhf(v1); v2 = tanhf(v2); v3 = tanhf(v3); }
    *(float4*)(Y + (size_t)i * 4) = make_float4(v0, v1, v2, v3);
}

// BN apply + write fp32 AND split bf16
__global__ void bn_apply_split_kernel(const float* __restrict__ X, float* __restrict__ Y,
                                      __nv_bfloat16* __restrict__ Yh,
                                      __nv_bfloat16* __restrict__ Yl,
                                      const float* __restrict__ mean,
                                      const float* __restrict__ rstd,
                                      const float* __restrict__ g,
                                      const float* __restrict__ b)
{
    int i = blockIdx.x * blockDim.x + threadIdx.x;
    if (i >= N_SRC * (D_DIM / 4)) return;
    int c0 = (i * 4) & (D_DIM - 1);
    float4 x = *(const float4*)(X + (size_t)i * 4);
    float v0 = (x.x - mean[c0 + 0]) * rstd[c0 + 0] * g[c0 + 0] + b[c0 + 0];
    float v1 = (x.y - mean[c0 + 1]) * rstd[c0 + 1] * g[c0 + 1] + b[c0 + 1];
    float v2 = (x.z - mean[c0 + 2]) * rstd[c0 + 2] * g[c0 + 2] + b[c0 + 2];
    float v3 = (x.w - mean[c0 + 3]) * rstd[c0 + 3] * g[c0 + 3] + b[c0 + 3];
    *(float4*)(Y + (size_t)i * 4) = make_float4(v0, v1, v2, v3);
    __nv_bfloat162 h0, l0, h1, l1;
    split2(v0, v1, h0, l0);
    split2(v2, v3, h1, l1);
    *(__nv_bfloat162*)(Yh + (size_t)i * 4)     = h0;
    *(__nv_bfloat162*)(Yh + (size_t)i * 4 + 2) = h1;
    *(__nv_bfloat162*)(Yl + (size_t)i * 4)     = l0;
    *(__nv_bfloat162*)(Yl + (size_t)i * 4 + 2) = l1;
}

__global__ void add_kernel(float* __restrict__ A, const float* __restrict__ B, int n4)
{
    int i = blockIdx.x * blockDim.x + threadIdx.x;
    if (i >= n4) return;
    float4 a = *(float4*)(A + (size_t)i * 4);
    float4 b = *(const float4*)(B + (size_t)i * 4);
    a.x += b.x; a.y += b.y; a.z += b.z; a.w += b.w;
    *(float4*)(A + (size_t)i * 4) = a;
}

// ---------------------------------------------------------------------------
// launch
// ---------------------------------------------------------------------------
#define GS_SMEM (8 * GS_TILE_B)   // 81920 bytes

extern "C" void kernel_launch(void* const* d_in, const int* in_sizes, int n_in,
                              void* d_out, int out_size)
{
    const float* src    = (const float*)d_in[0];
    const float* anchor = (const float*)d_in[1];
    const float* W_dim  = (const float*)d_in[2];
    const float* b_dim  = (const float*)d_in[3];
    const float* W_fus  = (const float*)d_in[4];
    const float* b_fus  = (const float*)d_in[5];
    const float* W_e1   = (const float*)d_in[6];
    const float* b_e1   = (const float*)d_in[7];
    const float* W_e2   = (const float*)d_in[8];
    const float* b_e2   = (const float*)d_in[9];
    const float* g1     = (const float*)d_in[10];
    const float* bt1    = (const float*)d_in[11];
    const float* g2     = (const float*)d_in[12];
    const float* bt2    = (const float*)d_in[13];
    const float* W_d    = (const float*)d_in[14];
    const float* b_d    = (const float*)d_in[15];
    const float* g_d    = (const float*)d_in[16];
    const float* bt_d   = (const float*)d_in[17];
    float* out = (float*)d_out;

    float *dots, *anorm, *comb, *tbuf, *zbuf, *ps, *qs, *mean, *rstd;
    int* idx;
    __nv_bfloat16 *src_bf, *anc_bf;
    __nv_bfloat16 *catA_hi, *catA_lo, *neigh_hi, *neigh_lo;
    __nv_bfloat16 *comb_hi, *comb_lo, *hid_hi, *hid_lo;
    __nv_bfloat16 *WdimT_hi, *WdimT_lo, *WfusT_hi, *WfusT_lo;
    __nv_bfloat16 *We1T_hi, *We1T_lo, *We2T_hi, *We2T_lo, *WdT_hi, *WdT_lo;

    cudaGetSymbolAddress((void**)&dots,     g_dots);
    cudaGetSymbolAddress((void**)&anorm,    g_anorm);
    cudaGetSymbolAddress((void**)&idx,      g_idx);
    cudaGetSymbolAddress((void**)&comb,     g_comb);
    cudaGetSymbolAddress((void**)&tbuf,     g_tbuf);
    cudaGetSymbolAddress((void**)&zbuf,     g_zbuf);
    cudaGetSymbolAddress((void**)&ps,       g_ps);
    cudaGetSymbolAddress((void**)&qs,       g_qs);
    cudaGetSymbolAddress((void**)&mean,     g_mean);
    cudaGetSymbolAddress((void**)&rstd,     g_rstd);
    cudaGetSymbolAddress((void**)&src_bf,   g_src_bf);
    cudaGetSymbolAddress((void**)&anc_bf,   g_anc_bf);
    cudaGetSymbolAddress((void**)&catA_hi,  g_catA_hi);
    cudaGetSymbolAddress((void**)&catA_lo,  g_catA_lo);
    cudaGetSymbolAddress((void**)&neigh_hi, g_neigh_hi);
    cudaGetSymbolAddress((void**)&neigh_lo, g_neigh_lo);
    cudaGetSymbolAddress((void**)&comb_hi,  g_comb_hi);
    cudaGetSymbolAddress((void**)&comb_lo,  g_comb_lo);
    cudaGetSymbolAddress((void**)&hid_hi,   g_hid_hi);
    cudaGetSymbolAddress((void**)&hid_lo,   g_hid_lo);
    cudaGetSymbolAddress((void**)&WdimT_hi, g_WdimT_hi);
    cudaGetSymbolAddress((void**)&WdimT_lo, g_WdimT_lo);
    cudaGetSymbolAddress((void**)&WfusT_hi, g_WfusT_hi);
    cudaGetSymbolAddress((void**)&WfusT_lo, g_WfusT_lo);
    cudaGetSymbolAddress((void**)&We1T_hi,  g_We1T_hi);
    cudaGetSymbolAddress((void**)&We1T_lo,  g_We1T_lo);
    cudaGetSymbolAddress((void**)&We2T_hi,  g_We2T_hi);
    cudaGetSymbolAddress((void**)&We2T_lo,  g_We2T_lo);
    cudaGetSymbolAddress((void**)&WdT_hi,   g_WdT_hi);
    cudaGetSymbolAddress((void**)&WdT_lo,   g_WdT_lo);

    cudaFuncSetAttribute(gemm_split_kernel<false, false, true>,
                         cudaFuncAttributeMaxDynamicSharedMemorySize, GS_SMEM);
    cudaFuncSetAttribute(gemm_split_kernel<false, true, false>,
                         cudaFuncAttributeMaxDynamicSharedMemorySize, GS_SMEM);
    cudaFuncSetAttribute(gemm_split_kernel<true, false, true>,
                         cudaFuncAttributeMaxDynamicSharedMemorySize, GS_SMEM);

    const int ND4 = N_SRC * (D_DIM / 4);

    // 0. conversions + weight transposes
    tobf16_kernel<<<(N_SRC * D_DIM / 4 + 255) / 256, 256>>>(src, src_bf, N_SRC * D_DIM / 4);
    tobf16_kernel<<<(M_ANC * D_DIM / 4 + 255) / 256, 256>>>(anchor, anc_bf, M_ANC * D_DIM / 4);
    split_src_kernel<<<(ND4 + 255) / 256, 256>>>(src, catA_hi, catA_lo);
    transpose_split_kernel<<<dim3(512 / 32, 512 / 32),  dim3(32, 8)>>>(W_dim, WdimT_hi, WdimT_lo, 512, 512);
    transpose_split_kernel<<<dim3(512 / 32, 1024 / 32), dim3(32, 8)>>>(W_fus, WfusT_hi, WfusT_lo, 1024, 512);
    transpose_split_kernel<<<dim3(2048 / 32, 512 / 32), dim3(32, 8)>>>(W_e1, We1T_hi, We1T_lo, 512, 2048);
    transpose_split_kernel<<<dim3(512 / 32, 2048 / 32), dim3(32, 8)>>>(W_e2, We2T_hi, We2T_lo, 2048, 512);
    transpose_split_kernel<<<dim3(512 / 32, 512 / 32),  dim3(32, 8)>>>(W_d, WdT_hi, WdT_lo, 512, 512);

    // 1. anchor norms
    anorm_kernel<<<(M_ANC * 32 + 255) / 256, 256>>>(anchor, anorm);

    // 2. dots = src @ anchor^T
    dist_gemm_bf16_kernel<<<dim3(M_ANC / 128, N_SRC / 128), 256>>>(src_bf, anc_bf, dots);

    // 3. top-5 with fp32 refinement
    topk_refine_kernel<<<(N_SRC * 32) / 256, 256>>>(dots, anorm, src, anchor, idx);

    // 4. gather + mean -> neigh split
    gather_mean_split_kernel<<<(ND4 + 255) / 256, 256>>>(anchor, idx, neigh_hi, neigh_lo);

    // 5. amap = neigh @ W_dim + b_dim  -> catA cols [512,1024)
    gemm_split_kernel<false, false, true><<<dim3(512 / 128, N_SRC / 128), 256, GS_SMEM>>>(
        neigh_hi, neigh_lo, WdimT_hi, WdimT_lo, b_dim,
        nullptr, catA_hi + 512, catA_lo + 512, 1024, 512, 512);

    // 6. comb = [src|amap] @ W_fus + b_fus   (K=1024)
    gemm_split_kernel<false, true, false><<<dim3(512 / 128, N_SRC / 128), 256, GS_SMEM>>>(
        catA_hi, catA_lo, WfusT_hi, WfusT_lo, b_fus,
        comb, nullptr, nullptr, 512, 512, 1024);

    // 7. BN1 -> comb fp32 + comb split
    bn_stats_kernel<<<128, 512>>>(comb, ps, qs);
    bn_final_kernel<<<1, 512>>>(ps, qs, mean, rstd);
    bn_apply_split_kernel<<<(ND4 + 255) / 256, 256>>>(comb, comb, comb_hi, comb_lo,
                                                      mean, rstd, g1, bt1);

    // 8. hidden = tanh(comb @ W_e1 + b_e1) -> split
    gemm_split_kernel<true, false, true><<<dim3(F_DIM / 128, N_SRC / 128), 256, GS_SMEM>>>(
        comb_hi, comb_lo, We1T_hi, We1T_lo, b_e1,
        nullptr, hid_hi, hid_lo, F_DIM, F_DIM, 512);

    // 9. tbuf = hidden @ W_e2 + b_e2   (K=2048)
    gemm_split_kernel<false, true, false><<<dim3(512 / 128, N_SRC / 128), 256, GS_SMEM>>>(
        hid_hi, hid_lo, We2T_hi, We2T_lo, b_e2,
        tbuf, nullptr, nullptr, 512, 512, F_DIM);

    // 10. comb += tbuf ; BN2 -> comb fp32 + split
    add_kernel<<<(ND4 + 255) / 256, 256>>>(comb, tbuf, ND4);
    bn_stats_kernel<<<128, 512>>>(comb, ps, qs);
    bn_final_kernel<<<1, 512>>>(ps, qs, mean, rstd);
    bn_apply_split_kernel<<<(ND4 + 255) / 256, 256>>>(comb, comb, comb_hi, comb_lo,
                                                      mean, rstd, g2, bt2);

    // 11. zbuf = comb @ W_d + b_d ; out = tanh(BN(zbuf))
    gemm_split_kernel<false, true, false><<<dim3(512 / 128, N_SRC / 128), 256, GS_SMEM>>>(
        comb_hi, comb_lo, WdT_hi, WdT_lo, b_d,
        zbuf, nullptr, nullptr, 512, 512, 512);
    bn_stats_kernel<<<128, 512>>>(zbuf, ps, qs);
    bn_final_kernel<<<1, 512>>>(ps, qs, mean, rstd);
    bn_apply_kernel<true><<<(ND4 + 255) / 256, 256>>>(zbuf, out, mean, rstd, g_d, bt_d);
}

// round 10
// speedup vs baseline: 2.2061x; 1.0379x over previous
#include <cuda_runtime.h>
#include <cuda_bf16.h>
#include <math.h>
#include <float.h>
#include <stdint.h>

// Problem constants
#define N_SRC   16384
#define M_ANC   8192
#define D_DIM   512
#define F_DIM   2048
#define KNN_K   5
#define BN_EPS  1e-5f

// ---------------------------------------------------------------------------
// Scratch (static device allocations; no cudaMalloc allowed)
// ---------------------------------------------------------------------------
__device__ float g_dots[(size_t)N_SRC * M_ANC];     // 512 MB
__device__ float g_anorm[M_ANC];
__device__ int   g_idx[N_SRC * KNN_K];
__device__ float g_comb[(size_t)N_SRC * D_DIM];
__device__ float g_tbuf[(size_t)N_SRC * D_DIM];
__device__ float g_zbuf[(size_t)N_SRC * D_DIM];
__device__ float g_ps[128 * D_DIM];
__device__ float g_qs[128 * D_DIM];
__device__ float g_mean[D_DIM];
__device__ float g_rstd[D_DIM];
__device__ __nv_bfloat16 g_src_bf[(size_t)N_SRC * D_DIM];
__device__ __nv_bfloat16 g_anc_bf[(size_t)M_ANC * D_DIM];
// split operands
__device__ __nv_bfloat16 g_catA_hi[(size_t)N_SRC * 1024];   // [src | amap]
__device__ __nv_bfloat16 g_catA_lo[(size_t)N_SRC * 1024];
__device__ __nv_bfloat16 g_neigh_hi[(size_t)N_SRC * D_DIM];
__device__ __nv_bfloat16 g_neigh_lo[(size_t)N_SRC * D_DIM];
__device__ __nv_bfloat16 g_comb_hi[(size_t)N_SRC * D_DIM];
__device__ __nv_bfloat16 g_comb_lo[(size_t)N_SRC * D_DIM];
__device__ __nv_bfloat16 g_hid_hi[(size_t)N_SRC * F_DIM];
__device__ __nv_bfloat16 g_hid_lo[(size_t)N_SRC * F_DIM];
// transposed + split weights [N, K]
__device__ __nv_bfloat16 g_WdimT_hi[512 * 512],  g_WdimT_lo[512 * 512];
__device__ __nv_bfloat16 g_WfusT_hi[512 * 1024], g_WfusT_lo[512 * 1024];
__device__ __nv_bfloat16 g_We1T_hi[2048 * 512],  g_We1T_lo[2048 * 512];
__device__ __nv_bfloat16 g_We2T_hi[512 * 2048],  g_We2T_lo[512 * 2048];
__device__ __nv_bfloat16 g_WdT_hi[512 * 512],    g_WdT_lo[512 * 512];

// ---------------------------------------------------------------------------
// small helpers
// ---------------------------------------------------------------------------
__device__ __forceinline__ void split2(float v0, float v1,
                                       __nv_bfloat162& hi, __nv_bfloat162& lo)
{
    hi = __floats2bfloat162_rn(v0, v1);
    lo = __floats2bfloat162_rn(v0 - __bfloat162float(hi.x),
                               v1 - __bfloat162float(hi.y));
}

__device__ __forceinline__ void cp_async16(uint32_t saddr, const void* gaddr)
{
    asm volatile("cp.async.cg.shared.global [%0], [%1], 16;\n"
                 :: "r"(saddr), "l"(gaddr));
}
#define CP_COMMIT() asm volatile("cp.async.commit_group;\n" ::: "memory")
#define CP_WAIT0()  asm volatile("cp.async.wait_group 0;\n" ::: "memory")

__device__ __forceinline__ void mma_bf16(float* c, const uint32_t* a, const uint32_t* b)
{
    asm volatile(
        "mma.sync.aligned.m16n8k16.row.col.f32.bf16.bf16.f32 "
        "{%0,%1,%2,%3}, {%4,%5,%6,%7}, {%8,%9}, {%0,%1,%2,%3};"
        : "+f"(c[0]), "+f"(c[1]), "+f"(c[2]), "+f"(c[3])
        : "r"(a[0]), "r"(a[1]), "r"(a[2]), "r"(a[3]),
          "r"(b[0]), "r"(b[1]));
}

__device__ __forceinline__ void ldmatrix_x4(uint32_t* r, uint32_t saddr)
{
    asm volatile("ldmatrix.sync.aligned.m8n8.x4.shared.b16 {%0,%1,%2,%3}, [%4];"
                 : "=r"(r[0]), "=r"(r[1]), "=r"(r[2]), "=r"(r[3]) : "r"(saddr));
}
__device__ __forceinline__ void ldmatrix_x2(uint32_t* r, uint32_t saddr)
{
    asm volatile("ldmatrix.sync.aligned.m8n8.x2.shared.b16 {%0,%1}, [%2];"
                 : "=r"(r[0]), "=r"(r[1]) : "r"(saddr));
}

// ---------------------------------------------------------------------------
// conversions
// ---------------------------------------------------------------------------
__global__ void tobf16_kernel(const float* __restrict__ x,
                              __nv_bfloat16* __restrict__ y, int n4)
{
    int i = blockIdx.x * blockDim.x + threadIdx.x;
    if (i >= n4) return;
    float4 v = *(const float4*)(x + (size_t)i * 4);
    __nv_bfloat162* o = (__nv_bfloat162*)(y + (size_t)i * 4);
    o[0] = __floats2bfloat162_rn(v.x, v.y);
    o[1] = __floats2bfloat162_rn(v.z, v.w);
}

// src [N,512] fp32 -> catA hi/lo cols [0,512) of a [N,1024] buffer
__global__ void split_src_kernel(const float* __restrict__ x,
                                 __nv_bfloat16* __restrict__ yh,
                                 __nv_bfloat16* __restrict__ yl)
{
    int i = blockIdx.x * blockDim.x + threadIdx.x;     // over N*128
    if (i >= N_SRC * (D_DIM / 4)) return;
    int n = i >> 7;
    int c = (i & 127) * 4;
    float4 v = *(const float4*)(x + (size_t)n * D_DIM + c);
    __nv_bfloat162 h0, l0, h1, l1;
    split2(v.x, v.y, h0, l0);
    split2(v.z, v.w, h1, l1);
    size_t o = (size_t)n * 1024 + c;
    *(__nv_bfloat162*)(yh + o)     = h0;
    *(__nv_bfloat162*)(yh + o + 2) = h1;
    *(__nv_bfloat162*)(yl + o)     = l0;
    *(__nv_bfloat162*)(yl + o + 2) = l1;
}

// W [K,N] fp32 -> T_hi/T_lo [N,K] bf16
__global__ void transpose_split_kernel(const float* __restrict__ W,
                                       __nv_bfloat16* __restrict__ Th,
                                       __nv_bfloat16* __restrict__ Tl,
                                       int K, int N)
{
    __shared__ float t[32][33];
    int n0 = blockIdx.x * 32, k0 = blockIdx.y * 32;
    int tx = threadIdx.x, ty = threadIdx.y;    // 32 x 8
    #pragma unroll
    for (int r = 0; r < 4; r++)
        t[ty + r * 8][tx] = W[(size_t)(k0 + ty + r * 8) * N + n0 + tx];
    __syncthreads();
    #pragma unroll
    for (int r = 0; r < 4; r++) {
        float v = t[tx][ty + r * 8];
        __nv_bfloat16 h = __float2bfloat16(v);
        Th[(size_t)(n0 + ty + r * 8) * K + k0 + tx] = h;
        Tl[(size_t)(n0 + ty + r * 8) * K + k0 + tx] =
            __float2bfloat16(v - __bfloat162float(h));
    }
}

// ===========================================================================
// Split-bf16 GEMM: C[M,N] = (Ahi+Alo)[M,K] @ (Bhi+Blo)[N,K]^T + bias
// 3-term MMA (hi*hi + hi*lo + lo*hi), fp32 accum.
// CTA 128x128, 4 warps 2(M)x2(N), warp tile 64x64 (LDS-traffic optimal).
// BK=32, cp.async double buffer (80KB dynamic smem).
// ===========================================================================
#define GS_TILE_B 10240          // 128 rows * 80 bytes

// loader: 128 threads; thread t fills row t (4x 16B quarters) of all 4 tiles
__device__ __forceinline__ void gs_load_chunk(
    uint32_t sbase, int buf,
    const __nv_bfloat16* gAh, const __nv_bfloat16* gAl,
    const __nv_bfloat16* gBh, const __nv_bfloat16* gBl,
    int t, int kt, int K)
{
    uint32_t b = sbase + (uint32_t)buf * (4 * GS_TILE_B);
    uint32_t ro = (uint32_t)(t * 80);
    const __nv_bfloat16* ah = gAh + (size_t)t * K + kt;
    const __nv_bfloat16* al = gAl + (size_t)t * K + kt;
    const __nv_bfloat16* bh = gBh + (size_t)t * K + kt;
    const __nv_bfloat16* bl = gBl + (size_t)t * K + kt;
    #pragma unroll
    for (int q = 0; q < 4; q++) {
        cp_async16(b + 0 * GS_TILE_B + ro + q * 16, ah + q * 8);
        cp_async16(b + 1 * GS_TILE_B + ro + q * 16, al + q * 8);
        cp_async16(b + 2 * GS_TILE_B + ro + q * 16, bh + q * 8);
        cp_async16(b + 3 * GS_TILE_B + ro + q * 16, bl + q * 8);
    }
}

template<bool TANH, bool OUT32, bool OUTSPLIT>
__global__ void __launch_bounds__(128) gemm_split_kernel(
    const __nv_bfloat16* __restrict__ Ahi, const __nv_bfloat16* __restrict__ Alo,
    const __nv_bfloat16* __restrict__ Bhi, const __nv_bfloat16* __restrict__ Blo,
    const float* __restrict__ bias,
    float* __restrict__ C32,
    __nv_bfloat16* __restrict__ Chi, __nv_bfloat16* __restrict__ Clo,
    int ldC, int N, int K)
{
    extern __shared__ __nv_bfloat16 smem[];
    uint32_t sb = (uint32_t)__cvta_generic_to_shared(smem);

    int tid = threadIdx.x;
    int lane = tid & 31;
    int wid = tid >> 5;
    int warp_m = wid >> 1;     // 0..1
    int warp_n = wid & 1;      // 0..1
    int bx = blockIdx.x;
    int by = blockIdx.y;

    const __nv_bfloat16* gAh = Ahi + (size_t)(by * 128) * K;
    const __nv_bfloat16* gAl = Alo + (size_t)(by * 128) * K;
    const __nv_bfloat16* gBh = Bhi + (size_t)(bx * 128) * K;
    const __nv_bfloat16* gBl = Blo + (size_t)(bx * 128) * K;

    float acc[4][8][4];
    #pragma unroll
    for (int i = 0; i < 4; i++)
        #pragma unroll
        for (int j = 0; j < 8; j++)
            #pragma unroll
            for (int e = 0; e < 4; e++) acc[i][j][e] = 0.f;

    gs_load_chunk(sb, 0, gAh, gAl, gBh, gBl, tid, 0, K);
    CP_COMMIT();
    CP_WAIT0();
    __syncthreads();

    const int KIT = K / 32;
    for (int it = 0; it < KIT; it++) {
        int cur = it & 1;
        if (it + 1 < KIT) {
            gs_load_chunk(sb, cur ^ 1, gAh, gAl, gBh, gBl, tid, (it + 1) * 32, K);
            CP_COMMIT();
        }

        uint32_t tAh = sb + (uint32_t)cur * (4 * GS_TILE_B);
        uint32_t tAl = tAh + GS_TILE_B;
        uint32_t tBh = tAh + 2 * GS_TILE_B;
        uint32_t tBl = tAh + 3 * GS_TILE_B;

        #pragma unroll
        for (int ks = 0; ks < 2; ks++) {
            uint32_t afh[4][4], afl[4][4];
            int arow = (lane & 7) + 8 * ((lane >> 3) & 1);
            int acol = ks * 32 + 16 * (lane >> 4);
            #pragma unroll
            for (int i = 0; i < 4; i++) {
                int row = warp_m * 64 + i * 16 + arow;
                ldmatrix_x4(afh[i], tAh + (uint32_t)(row * 80 + acol));
                ldmatrix_x4(afl[i], tAl + (uint32_t)(row * 80 + acol));
            }
            int brow = lane & 7;
            int bcol = ks * 32 + 16 * ((lane >> 3) & 1);
            #pragma unroll
            for (int j = 0; j < 8; j++) {
                uint32_t bfh[2], bfl[2];
                int row = warp_n * 64 + j * 8 + brow;
                ldmatrix_x2(bfh, tBh + (uint32_t)(row * 80 + bcol));
                ldmatrix_x2(bfl, tBl + (uint32_t)(row * 80 + bcol));
                #pragma unroll
                for (int i = 0; i < 4; i++) {
                    mma_bf16(acc[i][j], afh[i], bfh);
                    mma_bf16(acc[i][j], afh[i], bfl);
                    mma_bf16(acc[i][j], afl[i], bfh);
                }
            }
        }

        if (it + 1 < KIT) {
            CP_WAIT0();
            __syncthreads();
        }
    }

    // epilogue
    int row0 = by * 128 + warp_m * 64;
    int col0 = bx * 128 + warp_n * 64;
    #pragma unroll
    for (int i = 0; i < 4; i++) {
        int ra = row0 + i * 16 + (lane >> 2);
        #pragma unroll
        for (int j = 0; j < 8; j++) {
            int ca = col0 + j * 8 + (lane & 3) * 2;
            float b0 = bias[ca], b1 = bias[ca + 1];
            float v0 = acc[i][j][0] + b0, v1 = acc[i][j][1] + b1;
            float w0 = acc[i][j][2] + b0, w1 = acc[i][j][3] + b1;
            if (TANH) { v0 = tanhf(v0); v1 = tanhf(v1); w0 = tanhf(w0); w1 = tanhf(w1); }
            if (OUT32) {
                *(float2*)(C32 + (size_t)ra * ldC + ca)       = make_float2(v0, v1);
                *(float2*)(C32 + (size_t)(ra + 8) * ldC + ca) = make_float2(w0, w1);
            }
            if (OUTSPLIT) {
                __nv_bfloat162 h, l;
                split2(v0, v1, h, l);
                *(__nv_bfloat162*)(Chi + (size_t)ra * ldC + ca) = h;
                *(__nv_bfloat162*)(Clo + (size_t)ra * ldC + ca) = l;
                split2(w0, w1, h, l);
                *(__nv_bfloat162*)(Chi + (size_t)(ra + 8) * ldC + ca) = h;
                *(__nv_bfloat162*)(Clo + (size_t)(ra + 8) * ldC + ca) = l;
            }
        }
    }
}

// ===========================================================================
// Distance GEMM: bf16 ldmatrix + mma, CTA 128x128, 4 warps 2x2, warp 64x64,
// cp.async double buffer (40KB static smem).
// ===========================================================================
__global__ void __launch_bounds__(128) dist_gemm_bf16_kernel(
    const __nv_bfloat16* __restrict__ A,
    const __nv_bfloat16* __restrict__ B,
    float* __restrict__ C)
{
    __shared__ __nv_bfloat16 sA[2][128 * 40];
    __shared__ __nv_bfloat16 sB[2][128 * 40];

    int tid = threadIdx.x;
    int lane = tid & 31;
    int wid = tid >> 5;
    int warp_m = wid >> 1;
    int warp_n = wid & 1;
    int bx = blockIdx.x;
    int by = blockIdx.y;

    const __nv_bfloat16* Ag = A + (size_t)(by * 128) * D_DIM;
    const __nv_bfloat16* Bg = B + (size_t)(bx * 128) * D_DIM;

    uint32_t a_s[2], b_s[2];
    a_s[0] = (uint32_t)__cvta_generic_to_shared(&sA[0][0]);
    a_s[1] = (uint32_t)__cvta_generic_to_shared(&sA[1][0]);
    b_s[0] = (uint32_t)__cvta_generic_to_shared(&sB[0][0]);
    b_s[1] = (uint32_t)__cvta_generic_to_shared(&sB[1][0]);

    float acc[4][8][4];
    #pragma unroll
    for (int i = 0; i < 4; i++)
        #pragma unroll
        for (int j = 0; j < 8; j++)
            #pragma unroll
            for (int e = 0; e < 4; e++) acc[i][j][e] = 0.f;

    // loader: thread t -> row t, 4 quarters of A and B
    {
        uint32_t ro = (uint32_t)(tid * 80);
        #pragma unroll
        for (int q = 0; q < 4; q++) {
            cp_async16(a_s[0] + ro + q * 16, Ag + (size_t)tid * D_DIM + q * 8);
            cp_async16(b_s[0] + ro + q * 16, Bg + (size_t)tid * D_DIM + q * 8);
        }
    }
    CP_COMMIT();
    CP_WAIT0();
    __syncthreads();

    const int KIT = D_DIM / 32;   // 16
    for (int it = 0; it < KIT; it++) {
        int cur = it & 1;
        if (it + 1 < KIT) {
            int kt = (it + 1) * 32;
            uint32_t ro = (uint32_t)(tid * 80);
            #pragma unroll
            for (int q = 0; q < 4; q++) {
                cp_async16(a_s[cur ^ 1] + ro + q * 16, Ag + (size_t)tid * D_DIM + kt + q * 8);
                cp_async16(b_s[cur ^ 1] + ro + q * 16, Bg + (size_t)tid * D_DIM + kt + q * 8);
            }
            CP_COMMIT();
        }

        #pragma unroll
        for (int ks = 0; ks < 2; ks++) {
            uint32_t af[4][4];
            int arow = (lane & 7) + 8 * ((lane >> 3) & 1);
            int acol = ks * 32 + 16 * (lane >> 4);
            #pragma unroll
            for (int i = 0; i < 4; i++) {
                int row = warp_m * 64 + i * 16 + arow;
                ldmatrix_x4(af[i], a_s[cur] + (uint32_t)(row * 80 + acol));
            }
            int brow = lane & 7;
            int bcol = ks * 32 + 16 * ((lane >> 3) & 1);
            #pragma unroll
            for (int j = 0; j < 8; j++) {
                uint32_t bf[2];
                int row = warp_n * 64 + j * 8 + brow;
                ldmatrix_x2(bf, b_s[cur] + (uint32_t)(row * 80 + bcol));
                #pragma unroll
                for (int i = 0; i < 4; i++)
                    mma_bf16(acc[i][j], af[i], bf);
            }
        }

        if (it + 1 < KIT) {
            CP_WAIT0();
            __syncthreads();
        }
    }

    int row0 = by * 128 + warp_m * 64;
    int col0 = bx * 128 + warp_n * 64;
    #pragma unroll
    for (int i = 0; i < 4; i++) {
        int ra = row0 + i * 16 + (lane >> 2);
        #pragma unroll
        for (int j = 0; j < 8; j++) {
            int ca = col0 + j * 8 + (lane & 3) * 2;
            *(float2*)(C + (size_t)ra * M_ANC + ca) =
                make_float2(acc[i][j][0], acc[i][j][1]);
            *(float2*)(C + (size_t)(ra + 8) * M_ANC + ca) =
                make_float2(acc[i][j][2], acc[i][j][3]);
        }
    }
}

// ---------------------------------------------------------------------------
// anchor squared norms
// ---------------------------------------------------------------------------
__global__ void anorm_kernel(const float* __restrict__ anchor, float* __restrict__ anorm) {
    int gw = (blockIdx.x * blockDim.x + threadIdx.x) >> 5;
    int lane = threadIdx.x & 31;
    if (gw >= M_ANC) return;
    const float* row = anchor + (size_t)gw * D_DIM;
    float s = 0.f;
    #pragma unroll
    for (int j = lane; j < D_DIM; j += 32) { float v = row[j]; s += v * v; }
    #pragma unroll
    for (int off = 16; off; off >>= 1) s += __shfl_xor_sync(0xffffffffu, s, off);
    if (lane == 0) anorm[gw] = s;
}

// ---------------------------------------------------------------------------
// top-5 with bf16->fp32 refinement (unchanged)
// ---------------------------------------------------------------------------
#define TK_MARGIN 2.5f
#define TK_MAXC   64

__global__ void __launch_bounds__(256) topk_refine_kernel(
    const float* __restrict__ dots,
    const float* __restrict__ anorm,
    const float* __restrict__ src,
    const float* __restrict__ anchor,
    int* __restrict__ idx_out)
{
    __shared__ int   s_cand[8][TK_MAXC];
    __shared__ float s_dval[8][TK_MAXC];

    int w = threadIdx.x >> 5;
    int row = (blockIdx.x * blockDim.x + threadIdx.x) >> 5;
    int lane = threadIdx.x & 31;
    if (row >= N_SRC) return;

    const float* drow = dots + (size_t)row * M_ANC;

    float best[KNN_K];
    int   bidx[KNN_K];
    #pragma unroll
    for (int i = 0; i < KNN_K; i++) { best[i] = FLT_MAX; bidx[i] = 0x7fffffff; }

    for (int m = lane; m < M_ANC; m += 32) {
        float d = anorm[m] - 2.f * drow[m];
        if (d < best[KNN_K - 1]) {
            int p = KNN_K - 1;
            #pragma unroll
            for (int q = KNN_K - 1; q > 0; q--) {
                if (d < best[q - 1]) { best[q] = best[q - 1]; bidx[q] = bidx[q - 1]; p = q - 1; }
            }
            best[p] = d; bidx[p] = m;
        }
    }

    float t5 = FLT_MAX;
    int head = 0;
    #pragma unroll
    for (int s = 0; s < KNN_K; s++) {
        float mv = (head < KNN_K) ? best[head] : FLT_MAX;
        int   mi = (head < KNN_K) ? bidx[head] : 0x7fffffff;
        #pragma unroll
        for (int off = 16; off; off >>= 1) {
            float ov = __shfl_xor_sync(0xffffffffu, mv, off);
            int   oi = __shfl_xor_sync(0xffffffffu, mi, off);
            if (ov < mv || (ov == mv && oi < mi)) { mv = ov; mi = oi; }
        }
        if (head < KNN_K && bidx[head] == mi) head++;
        t5 = mv;
    }
    float thresh = t5 + TK_MARGIN;

    int cnt = 0;
    for (int m = lane; m < M_ANC; m += 32) {
        float d = anorm[m] - 2.f * drow[m];
        bool pred = (d <= thresh);
        unsigned mask = __ballot_sync(0xffffffffu, pred);
        if (pred) {
            int pos = cnt + __popc(mask & ((1u << lane) - 1u));
            if (pos < TK_MAXC) s_cand[w][pos] = m;
        }
        cnt += __popc(mask);
    }
    if (cnt > TK_MAXC) cnt = TK_MAXC;
    __syncwarp();

    float sreg[D_DIM / 32];
    const float* srow = src + (size_t)row * D_DIM;
    #pragma unroll
    for (int j = 0; j < D_DIM / 32; j++) sreg[j] = srow[lane + 32 * j];

    for (int c = 0; c < cnt; c++) {
        int m = s_cand[w][c];
        const float* arow = anchor + (size_t)m * D_DIM;
        float s = 0.f;
        #pragma unroll
        for (int j = 0; j < D_DIM / 32; j++) s += sreg[j] * arow[lane + 32 * j];
        #pragma unroll
        for (int off = 16; off; off >>= 1) s += __shfl_xor_sync(0xffffffffu, s, off);
        if (lane == 0) s_dval[w][c] = anorm[m] - 2.f * s;
    }
    __syncwarp();

    if (lane == 0) {
        #pragma unroll
        for (int s = 0; s < KNN_K; s++) {
            float mv = FLT_MAX; int mi = 0x7fffffff; int mc = -1;
            for (int c = 0; c < cnt; c++) {
                float v = s_dval[w][c]; int id = s_cand[w][c];
                if (v < mv || (v == mv && id < mi)) { mv = v; mi = id; mc = c; }
            }
            idx_out[row * KNN_K + s] = mi;
            if (mc >= 0) s_dval[w][mc] = FLT_MAX;
        }
    }
}

// ---------------------------------------------------------------------------
// gather + mean -> split bf16 output
// ---------------------------------------------------------------------------
__global__ void gather_mean_split_kernel(const float* __restrict__ anchor,
                                         const int* __restrict__ idx,
                                         __nv_bfloat16* __restrict__ yh,
                                         __nv_bfloat16* __restrict__ yl)
{
    int i = blockIdx.x * blockDim.x + threadIdx.x;
    if (i >= N_SRC * (D_DIM / 4)) return;
    int n = i / (D_DIM / 4);
    int d4 = (i % (D_DIM / 4)) * 4;
    const int* ix = idx + n * KNN_K;
    float4 a = make_float4(0.f, 0.f, 0.f, 0.f);
    #pragma unroll
    for (int k = 0; k < KNN_K; k++) {
        float4 v = *(const float4*)(anchor + (size_t)ix[k] * D_DIM + d4);
        a.x += v.x; a.y += v.y; a.z += v.z; a.w += v.w;
    }
    const float inv = 1.f / (float)KNN_K;
    a.x *= inv; a.y *= inv; a.z *= inv; a.w *= inv;
    __nv_bfloat162 h0, l0, h1, l1;
    split2(a.x, a.y, h0, l0);
    split2(a.z, a.w, h1, l1);
    size_t o = (size_t)n * D_DIM + d4;
    *(__nv_bfloat162*)(yh + o)     = h0;
    *(__nv_bfloat162*)(yh + o + 2) = h1;
    *(__nv_bfloat162*)(yl + o)     = l0;
    *(__nv_bfloat162*)(yl + o + 2) = l1;
}

// ---------------------------------------------------------------------------
// BatchNorm
// ---------------------------------------------------------------------------
__global__ void bn_stats_kernel(const float* __restrict__ X,
                                float* __restrict__ ps, float* __restrict__ qs)
{
    int c = threadIdx.x;
    int r0 = blockIdx.x * 128;
    float s = 0.f, q = 0.f;
    #pragma unroll 4
    for (int r = 0; r < 128; r++) {
        float v = X[(size_t)(r0 + r) * D_DIM + c];
        s += v; q += v * v;
    }
    ps[blockIdx.x * D_DIM + c] = s;
    qs[blockIdx.x * D_DIM + c] = q;
}

__global__ void bn_final_kernel(const float* __restrict__ ps, const float* __restrict__ qs,
                                float* __restrict__ mean, float* __restrict__ rstd)
{
    int c = threadIdx.x;
    float s = 0.f, q = 0.f;
    #pragma unroll 8
    for (int b = 0; b < 128; b++) { s += ps[b * D_DIM + c]; q += qs[b * D_DIM + c]; }
    float m = s * (1.f / (float)N_SRC);
    float v = q * (1.f / (float)N_SRC) - m * m;
    mean[c] = m;
    rstd[c] = rsqrtf(v + BN_EPS);
}

template<bool TANH>
__global__ void bn_apply_kernel(const float* __restrict__ X, float* __restrict__ Y,
                                const float* __restrict__ mean, const float* __restrict__ rstd,
                                const float* __restrict__ g, const float* __restrict__ b)
{
    int i = blockIdx.x * blockDim.x + threadIdx.x;
    if (i >= N_SRC * (D_DIM / 4)) return;
    int c0 = (i * 4) & (D_DIM - 1);
    float4 x = *(const float4*)(X + (size_t)i * 4);
    float v0 = (x.x - mean[c0 + 0]) * rstd[c0 + 0] * g[c0 + 0] + b[c0 + 0];
    float v1 = (x.y - mean[c0 + 1]) * rstd[c0 + 1] * g[c0 + 1] + b[c0 + 1];
    float v2 = (x.z - mean[c0 + 2]) * rstd[c0 + 2] * g[c0 + 2] + b[c0 + 2];
    float v3 = (x.w - mean[c0 + 3]) * rstd[c0 + 3] * g[c0 + 3] + b[c0 + 3];
    if (TANH) { v0 = tanhf(v0); v1 = tanhf(v1); v2 = tanhf(v2); v3 = tanhf(v3); }
    *(float4*)(Y + (size_t)i * 4) = make_float4(v0, v1, v2, v3);
}

// BN apply + write fp32 AND split bf16
__global__ void bn_apply_split_kernel(const float* __restrict__ X, float* __restrict__ Y,
                                      __nv_bfloat16* __restrict__ Yh,
                                      __nv_bfloat16* __restrict__ Yl,
                                      const float* __restrict__ mean,
                                      const float* __restrict__ rstd,
                                      const float* __restrict__ g,
                                      const float* __restrict__ b)
{
    int i = blockIdx.x * blockDim.x + threadIdx.x;
    if (i >= N_SRC * (D_DIM / 4)) return;
    int c0 = (i * 4) & (D_DIM - 1);
    float4 x = *(const float4*)(X + (size_t)i * 4);
    float v0 = (x.x - mean[c0 + 0]) * rstd[c0 + 0] * g[c0 + 0] + b[c0 + 0];
    float v1 = (x.y - mean[c0 + 1]) * rstd[c0 + 1] * g[c0 + 1] + b[c0 + 1];
    float v2 = (x.z - mean[c0 + 2]) * rstd[c0 + 2] * g[c0 + 2] + b[c0 + 2];
    float v3 = (x.w - mean[c0 + 3]) * rstd[c0 + 3] * g[c0 + 3] + b[c0 + 3];
    *(float4*)(Y + (size_t)i * 4) = make_float4(v0, v1, v2, v3);
    __nv_bfloat162 h0, l0, h1, l1;
    split2(v0, v1, h0, l0);
    split2(v2, v3, h1, l1);
    *(__nv_bfloat162*)(Yh + (size_t)i * 4)     = h0;
    *(__nv_bfloat162*)(Yh + (size_t)i * 4 + 2) = h1;
    *(__nv_bfloat162*)(Yl + (size_t)i * 4)     = l0;
    *(__nv_bfloat162*)(Yl + (size_t)i * 4 + 2) = l1;
}

__global__ void add_kernel(float* __restrict__ A, const float* __restrict__ B, int n4)
{
    int i = blockIdx.x * blockDim.x + threadIdx.x;
    if (i >= n4) return;
    float4 a = *(float4*)(A + (size_t)i * 4);
    float4 b = *(const float4*)(B + (size_t)i * 4);
    a.x += b.x; a.y += b.y; a.z += b.z; a.w += b.w;
    *(float4*)(A + (size_t)i * 4) = a;
}

// ---------------------------------------------------------------------------
// launch
// ---------------------------------------------------------------------------
#define GS_SMEM (8 * GS_TILE_B)   // 81920 bytes

extern "C" void kernel_launch(void* const* d_in, const int* in_sizes, int n_in,
                              void* d_out, int out_size)
{
    const float* src    = (const float*)d_in[0];
    const float* anchor = (const float*)d_in[1];
    const float* W_dim  = (const float*)d_in[2];
    const float* b_dim  = (const float*)d_in[3];
    const float* W_fus  = (const float*)d_in[4];
    const float* b_fus  = (const float*)d_in[5];
    const float* W_e1   = (const float*)d_in[6];
    const float* b_e1   = (const float*)d_in[7];
    const float* W_e2   = (const float*)d_in[8];
    const float* b_e2   = (const float*)d_in[9];
    const float* g1     = (const float*)d_in[10];
    const float* bt1    = (const float*)d_in[11];
    const float* g2     = (const float*)d_in[12];
    const float* bt2    = (const float*)d_in[13];
    const float* W_d    = (const float*)d_in[14];
    const float* b_d    = (const float*)d_in[15];
    const float* g_d    = (const float*)d_in[16];
    const float* bt_d   = (const float*)d_in[17];
    float* out = (float*)d_out;

    float *dots, *anorm, *comb, *tbuf, *zbuf, *ps, *qs, *mean, *rstd;
    int* idx;
    __nv_bfloat16 *src_bf, *anc_bf;
    __nv_bfloat16 *catA_hi, *catA_lo, *neigh_hi, *neigh_lo;
    __nv_bfloat16 *comb_hi, *comb_lo, *hid_hi, *hid_lo;
    __nv_bfloat16 *WdimT_hi, *WdimT_lo, *WfusT_hi, *WfusT_lo;
    __nv_bfloat16 *We1T_hi, *We1T_lo, *We2T_hi, *We2T_lo, *WdT_hi, *WdT_lo;

    cudaGetSymbolAddress((void**)&dots,     g_dots);
    cudaGetSymbolAddress((void**)&anorm,    g_anorm);
    cudaGetSymbolAddress((void**)&idx,      g_idx);
    cudaGetSymbolAddress((void**)&comb,     g_comb);
    cudaGetSymbolAddress((void**)&tbuf,     g_tbuf);
    cudaGetSymbolAddress((void**)&zbuf,     g_zbuf);
    cudaGetSymbolAddress((void**)&ps,       g_ps);
    cudaGetSymbolAddress((void**)&qs,       g_qs);
    cudaGetSymbolAddress((void**)&mean,     g_mean);
    cudaGetSymbolAddress((void**)&rstd,     g_rstd);
    cudaGetSymbolAddress((void**)&src_bf,   g_src_bf);
    cudaGetSymbolAddress((void**)&anc_bf,   g_anc_bf);
    cudaGetSymbolAddress((void**)&catA_hi,  g_catA_hi);
    cudaGetSymbolAddress((void**)&catA_lo,  g_catA_lo);
    cudaGetSymbolAddress((void**)&neigh_hi, g_neigh_hi);
    cudaGetSymbolAddress((void**)&neigh_lo, g_neigh_lo);
    cudaGetSymbolAddress((void**)&comb_hi,  g_comb_hi);
    cudaGetSymbolAddress((void**)&comb_lo,  g_comb_lo);
    cudaGetSymbolAddress((void**)&hid_hi,   g_hid_hi);
    cudaGetSymbolAddress((void**)&hid_lo,   g_hid_lo);
    cudaGetSymbolAddress((void**)&WdimT_hi, g_WdimT_hi);
    cudaGetSymbolAddress((void**)&WdimT_lo, g_WdimT_lo);
    cudaGetSymbolAddress((void**)&WfusT_hi, g_WfusT_hi);
    cudaGetSymbolAddress((void**)&WfusT_lo, g_WfusT_lo);
    cudaGetSymbolAddress((void**)&We1T_hi,  g_We1T_hi);
    cudaGetSymbolAddress((void**)&We1T_lo,  g_We1T_lo);
    cudaGetSymbolAddress((void**)&We2T_hi,  g_We2T_hi);
    cudaGetSymbolAddress((void**)&We2T_lo,  g_We2T_lo);
    cudaGetSymbolAddress((void**)&WdT_hi,   g_WdT_hi);
    cudaGetSymbolAddress((void**)&WdT_lo,   g_WdT_lo);

    cudaFuncSetAttribute(gemm_split_kernel<false, false, true>,
                         cudaFuncAttributeMaxDynamicSharedMemorySize, GS_SMEM);
    cudaFuncSetAttribute(gemm_split_kernel<false, true, false>,
                         cudaFuncAttributeMaxDynamicSharedMemorySize, GS_SMEM);
    cudaFuncSetAttribute(gemm_split_kernel<true, false, true>,
                         cudaFuncAttributeMaxDynamicSharedMemorySize, GS_SMEM);

    const int ND4 = N_SRC * (D_DIM / 4);

    // 0. conversions + weight transposes
    tobf16_kernel<<<(N_SRC * D_DIM / 4 + 255) / 256, 256>>>(src, src_bf, N_SRC * D_DIM / 4);
    tobf16_kernel<<<(M_ANC * D_DIM / 4 + 255) / 256, 256>>>(anchor, anc_bf, M_ANC * D_DIM / 4);
    split_src_kernel<<<(ND4 + 255) / 256, 256>>>(src, catA_hi, catA_lo);
    transpose_split_kernel<<<dim3(512 / 32, 512 / 32),  dim3(32, 8)>>>(W_dim, WdimT_hi, WdimT_lo, 512, 512);
    transpose_split_kernel<<<dim3(512 / 32, 1024 / 32), dim3(32, 8)>>>(W_fus, WfusT_hi, WfusT_lo, 1024, 512);
    transpose_split_kernel<<<dim3(2048 / 32, 512 / 32), dim3(32, 8)>>>(W_e1, We1T_hi, We1T_lo, 512, 2048);
    transpose_split_kernel<<<dim3(512 / 32, 2048 / 32), dim3(32, 8)>>>(W_e2, We2T_hi, We2T_lo, 2048, 512);
    transpose_split_kernel<<<dim3(512 / 32, 512 / 32),  dim3(32, 8)>>>(W_d, WdT_hi, WdT_lo, 512, 512);

    // 1. anchor norms
    anorm_kernel<<<(M_ANC * 32 + 255) / 256, 256>>>(anchor, anorm);

    // 2. dots = src @ anchor^T
    dist_gemm_bf16_kernel<<<dim3(M_ANC / 128, N_SRC / 128), 128>>>(src_bf, anc_bf, dots);

    // 3. top-5 with fp32 refinement
    topk_refine_kernel<<<(N_SRC * 32) / 256, 256>>>(dots, anorm, src, anchor, idx);

    // 4. gather + mean -> neigh split
    gather_mean_split_kernel<<<(ND4 + 255) / 256, 256>>>(anchor, idx, neigh_hi, neigh_lo);

    // 5. amap = neigh @ W_dim + b_dim  -> catA cols [512,1024)
    gemm_split_kernel<false, false, true><<<dim3(512 / 128, N_SRC / 128), 128, GS_SMEM>>>(
        neigh_hi, neigh_lo, WdimT_hi, WdimT_lo, b_dim,
        nullptr, catA_hi + 512, catA_lo + 512, 1024, 512, 512);

    // 6. comb = [src|amap] @ W_fus + b_fus   (K=1024)
    gemm_split_kernel<false, true, false><<<dim3(512 / 128, N_SRC / 128), 128, GS_SMEM>>>(
        catA_hi, catA_lo, WfusT_hi, WfusT_lo, b_fus,
        comb, nullptr, nullptr, 512, 512, 1024);

    // 7. BN1 -> comb fp32 + comb split
    bn_stats_kernel<<<128, 512>>>(comb, ps, qs);
    bn_final_kernel<<<1, 512>>>(ps, qs, mean, rstd);
    bn_apply_split_kernel<<<(ND4 + 255) / 256, 256>>>(comb, comb, comb_hi, comb_lo,
                                                      mean, rstd, g1, bt1);

    // 8. hidden = tanh(comb @ W_e1 + b_e1) -> split
    gemm_split_kernel<true, false, true><<<dim3(F_DIM / 128, N_SRC / 128), 128, GS_SMEM>>>(
        comb_hi, comb_lo, We1T_hi, We1T_lo, b_e1,
        nullptr, hid_hi, hid_lo, F_DIM, F_DIM, 512);

    // 9. tbuf = hidden @ W_e2 + b_e2   (K=2048)
    gemm_split_kernel<false, true, false><<<dim3(512 / 128, N_SRC / 128), 128, GS_SMEM>>>(
        hid_hi, hid_lo, We2T_hi, We2T_lo, b_e2,
        tbuf, nullptr, nullptr, 512, 512, F_DIM);

    // 10. comb += tbuf ; BN2 -> comb fp32 + split
    add_kernel<<<(ND4 + 255) / 256, 256>>>(comb, tbuf, ND4);
    bn_stats_kernel<<<128, 512>>>(comb, ps, qs);
    bn_final_kernel<<<1, 512>>>(ps, qs, mean, rstd);
    bn_apply_split_kernel<<<(ND4 + 255) / 256, 256>>>(comb, comb, comb_hi, comb_lo,
                                                      mean, rstd, g2, bt2);

    // 11. zbuf = comb @ W_d + b_d ; out = tanh(BN(zbuf))
    gemm_split_kernel<false, true, false><<<dim3(512 / 128, N_SRC / 128), 128, GS_SMEM>>>(
        comb_hi, comb_lo, WdT_hi, WdT_lo, b_d,
        zbuf, nullptr, nullptr, 512, 512, 512);
    bn_stats_kernel<<<128, 512>>>(zbuf, ps, qs);
    bn_final_kernel<<<1, 512>>>(ps, qs, mean, rstd);
    bn_apply_kernel<true><<<(ND4 + 255) / 256, 256>>>(zbuf, out, mean, rstd, g_d, bt_d);
}

// round 11
// speedup vs baseline: 2.2250x; 1.0086x over previous
#include <cuda_runtime.h>
#include <cuda_bf16.h>
#include <math.h>
#include <float.h>
#include <stdint.h>

// Problem constants
#define N_SRC   16384
#define M_ANC   8192
#define D_DIM   512
#define F_DIM   2048
#define KNN_K   5
#define BN_EPS  1e-5f

// ---------------------------------------------------------------------------
// Scratch (static device allocations; no cudaMalloc allowed)
// ---------------------------------------------------------------------------
__device__ float g_dots[(size_t)N_SRC * M_ANC];     // 512 MB
__device__ float g_anorm[M_ANC];
__device__ int   g_idx[N_SRC * KNN_K];
__device__ float g_comb[(size_t)N_SRC * D_DIM];
__device__ float g_tbuf[(size_t)N_SRC * D_DIM];
__device__ float g_zbuf[(size_t)N_SRC * D_DIM];
__device__ float g_ps[128 * D_DIM];
__device__ float g_qs[128 * D_DIM];
__device__ float g_mean[D_DIM];
__device__ float g_rstd[D_DIM];
__device__ __nv_bfloat16 g_src_bf[(size_t)N_SRC * D_DIM];
__device__ __nv_bfloat16 g_anc_bf[(size_t)M_ANC * D_DIM];
// split operands
__device__ __nv_bfloat16 g_catA_hi[(size_t)N_SRC * 1024];   // [src | amap]
__device__ __nv_bfloat16 g_catA_lo[(size_t)N_SRC * 1024];
__device__ __nv_bfloat16 g_neigh_hi[(size_t)N_SRC * D_DIM];
__device__ __nv_bfloat16 g_neigh_lo[(size_t)N_SRC * D_DIM];
__device__ __nv_bfloat16 g_comb_hi[(size_t)N_SRC * D_DIM];
__device__ __nv_bfloat16 g_comb_lo[(size_t)N_SRC * D_DIM];
__device__ __nv_bfloat16 g_hid_hi[(size_t)N_SRC * F_DIM];
__device__ __nv_bfloat16 g_hid_lo[(size_t)N_SRC * F_DIM];
// transposed + split weights [N, K]
__device__ __nv_bfloat16 g_WdimT_hi[512 * 512],  g_WdimT_lo[512 * 512];
__device__ __nv_bfloat16 g_WfusT_hi[512 * 1024], g_WfusT_lo[512 * 1024];
__device__ __nv_bfloat16 g_We1T_hi[2048 * 512],  g_We1T_lo[2048 * 512];
__device__ __nv_bfloat16 g_We2T_hi[512 * 2048],  g_We2T_lo[512 * 2048];
__device__ __nv_bfloat16 g_WdT_hi[512 * 512],    g_WdT_lo[512 * 512];

// ---------------------------------------------------------------------------
// small helpers
// ---------------------------------------------------------------------------
__device__ __forceinline__ void split2(float v0, float v1,
                                       __nv_bfloat162& hi, __nv_bfloat162& lo)
{
    hi = __floats2bfloat162_rn(v0, v1);
    lo = __floats2bfloat162_rn(v0 - __bfloat162float(hi.x),
                               v1 - __bfloat162float(hi.y));
}

__device__ __forceinline__ void cp_async16(uint32_t saddr, const void* gaddr)
{
    asm volatile("cp.async.cg.shared.global [%0], [%1], 16;\n"
                 :: "r"(saddr), "l"(gaddr));
}
#define CP_COMMIT() asm volatile("cp.async.commit_group;\n" ::: "memory")
#define CP_WAIT0()  asm volatile("cp.async.wait_group 0;\n" ::: "memory")

__device__ __forceinline__ void mma_bf16(float* c, const uint32_t* a, const uint32_t* b)
{
    asm volatile(
        "mma.sync.aligned.m16n8k16.row.col.f32.bf16.bf16.f32 "
        "{%0,%1,%2,%3}, {%4,%5,%6,%7}, {%8,%9}, {%0,%1,%2,%3};"
        : "+f"(c[0]), "+f"(c[1]), "+f"(c[2]), "+f"(c[3])
        : "r"(a[0]), "r"(a[1]), "r"(a[2]), "r"(a[3]),
          "r"(b[0]), "r"(b[1]));
}

__device__ __forceinline__ void ldmatrix_x4(uint32_t* r, uint32_t saddr)
{
    asm volatile("ldmatrix.sync.aligned.m8n8.x4.shared.b16 {%0,%1,%2,%3}, [%4];"
                 : "=r"(r[0]), "=r"(r[1]), "=r"(r[2]), "=r"(r[3]) : "r"(saddr));
}
__device__ __forceinline__ void ldmatrix_x2(uint32_t* r, uint32_t saddr)
{
    asm volatile("ldmatrix.sync.aligned.m8n8.x2.shared.b16 {%0,%1}, [%2];"
                 : "=r"(r[0]), "=r"(r[1]) : "r"(saddr));
}

// ---------------------------------------------------------------------------
// conversions
// ---------------------------------------------------------------------------
__global__ void tobf16_kernel(const float* __restrict__ x,
                              __nv_bfloat16* __restrict__ y, int n4)
{
    int i = blockIdx.x * blockDim.x + threadIdx.x;
    if (i >= n4) return;
    float4 v = *(const float4*)(x + (size_t)i * 4);
    __nv_bfloat162* o = (__nv_bfloat162*)(y + (size_t)i * 4);
    o[0] = __floats2bfloat162_rn(v.x, v.y);
    o[1] = __floats2bfloat162_rn(v.z, v.w);
}

// src [N,512] fp32 -> catA hi/lo cols [0,512) of a [N,1024] buffer
__global__ void split_src_kernel(const float* __restrict__ x,
                                 __nv_bfloat16* __restrict__ yh,
                                 __nv_bfloat16* __restrict__ yl)
{
    int i = blockIdx.x * blockDim.x + threadIdx.x;     // over N*128
    if (i >= N_SRC * (D_DIM / 4)) return;
    int n = i >> 7;
    int c = (i & 127) * 4;
    float4 v = *(const float4*)(x + (size_t)n * D_DIM + c);
    __nv_bfloat162 h0, l0, h1, l1;
    split2(v.x, v.y, h0, l0);
    split2(v.z, v.w, h1, l1);
    size_t o = (size_t)n * 1024 + c;
    *(__nv_bfloat162*)(yh + o)     = h0;
    *(__nv_bfloat162*)(yh + o + 2) = h1;
    *(__nv_bfloat162*)(yl + o)     = l0;
    *(__nv_bfloat162*)(yl + o + 2) = l1;
}

// W [K,N] fp32 -> T_hi/T_lo [N,K] bf16
__global__ void transpose_split_kernel(const float* __restrict__ W,
                                       __nv_bfloat16* __restrict__ Th,
                                       __nv_bfloat16* __restrict__ Tl,
                                       int K, int N)
{
    __shared__ float t[32][33];
    int n0 = blockIdx.x * 32, k0 = blockIdx.y * 32;
    int tx = threadIdx.x, ty = threadIdx.y;    // 32 x 8
    #pragma unroll
    for (int r = 0; r < 4; r++)
        t[ty + r * 8][tx] = W[(size_t)(k0 + ty + r * 8) * N + n0 + tx];
    __syncthreads();
    #pragma unroll
    for (int r = 0; r < 4; r++) {
        float v = t[tx][ty + r * 8];
        __nv_bfloat16 h = __float2bfloat16(v);
        Th[(size_t)(n0 + ty + r * 8) * K + k0 + tx] = h;
        Tl[(size_t)(n0 + ty + r * 8) * K + k0 + tx] =
            __float2bfloat16(v - __bfloat162float(h));
    }
}

// ===========================================================================
// Split-bf16 GEMM: C[M,N] = (Ahi+Alo)[M,K] @ (Bhi+Blo)[N,K]^T + bias
// 3-term MMA (hi*hi + hi*lo + lo*hi), fp32 accum.
// CTA tile 128(M) x 256(N), 8 warps 2(M)x4(N), warp tile 64x64.
// BK=32, cp.async double buffer (120KB dynamic smem).
// ===========================================================================
#define GS_AT_B  10240           // A tile bytes (128 rows * 80)
#define GS_BT_B  20480           // B tile bytes (256 rows * 80)
#define GS_BUF_B (2 * GS_AT_B + 2 * GS_BT_B)   // 61440 per buffer
#define GS_SMEM  (2 * GS_BUF_B)                // 122880

// loader: 256 threads; A rows split by half-block, B rows 1:1 (hi and lo)
__device__ __forceinline__ void gs_load_chunk(
    uint32_t sbase, int buf,
    const __nv_bfloat16* gAh, const __nv_bfloat16* gAl,
    const __nv_bfloat16* gBh, const __nv_bfloat16* gBl,
    int tid, int kt, int K)
{
    uint32_t b = sbase + (uint32_t)buf * GS_BUF_B;
    int ar = tid & 127;
    const __nv_bfloat16* arow =
        (tid < 128 ? gAh + (size_t)ar * K : gAl + (size_t)ar * K) + kt;
    uint32_t aoff = b + (tid < 128 ? 0u : (uint32_t)GS_AT_B) + (uint32_t)(ar * 80);
    const __nv_bfloat16* bh = gBh + (size_t)tid * K + kt;
    const __nv_bfloat16* bl = gBl + (size_t)tid * K + kt;
    uint32_t bhoff = b + 2 * GS_AT_B + (uint32_t)(tid * 80);
    uint32_t bloff = bhoff + GS_BT_B;
    #pragma unroll
    for (int q = 0; q < 4; q++) {
        cp_async16(aoff + q * 16, arow + q * 8);
        cp_async16(bhoff + q * 16, bh + q * 8);
        cp_async16(bloff + q * 16, bl + q * 8);
    }
}

template<bool TANH, bool OUT32, bool OUTSPLIT>
__global__ void __launch_bounds__(256) gemm_split_kernel(
    const __nv_bfloat16* __restrict__ Ahi, const __nv_bfloat16* __restrict__ Alo,
    const __nv_bfloat16* __restrict__ Bhi, const __nv_bfloat16* __restrict__ Blo,
    const float* __restrict__ bias,
    float* __restrict__ C32,
    __nv_bfloat16* __restrict__ Chi, __nv_bfloat16* __restrict__ Clo,
    int ldC, int N, int K)
{
    extern __shared__ __nv_bfloat16 smem[];
    uint32_t sb = (uint32_t)__cvta_generic_to_shared(smem);

    int tid = threadIdx.x;
    int lane = tid & 31;
    int wid = tid >> 5;
    int warp_m = wid >> 2;     // 0..1
    int warp_n = wid & 3;      // 0..3
    int bx = blockIdx.x;       // N tile (256)
    int by = blockIdx.y;       // M tile (128)

    const __nv_bfloat16* gAh = Ahi + (size_t)(by * 128) * K;
    const __nv_bfloat16* gAl = Alo + (size_t)(by * 128) * K;
    const __nv_bfloat16* gBh = Bhi + (size_t)(bx * 256) * K;
    const __nv_bfloat16* gBl = Blo + (size_t)(bx * 256) * K;

    float acc[4][8][4];
    #pragma unroll
    for (int i = 0; i < 4; i++)
        #pragma unroll
        for (int j = 0; j < 8; j++)
            #pragma unroll
            for (int e = 0; e < 4; e++) acc[i][j][e] = 0.f;

    gs_load_chunk(sb, 0, gAh, gAl, gBh, gBl, tid, 0, K);
    CP_COMMIT();
    CP_WAIT0();
    __syncthreads();

    const int KIT = K / 32;
    for (int it = 0; it < KIT; it++) {
        int cur = it & 1;
        if (it + 1 < KIT) {
            gs_load_chunk(sb, cur ^ 1, gAh, gAl, gBh, gBl, tid, (it + 1) * 32, K);
            CP_COMMIT();
        }

        uint32_t bufb = sb + (uint32_t)cur * GS_BUF_B;
        uint32_t tAh = bufb;
        uint32_t tAl = bufb + GS_AT_B;
        uint32_t tBh = bufb + 2 * GS_AT_B;
        uint32_t tBl = tBh + GS_BT_B;

        #pragma unroll
        for (int ks = 0; ks < 2; ks++) {
            uint32_t afh[4][4], afl[4][4];
            int arow = (lane & 7) + 8 * ((lane >> 3) & 1);
            int acol = ks * 32 + 16 * (lane >> 4);
            #pragma unroll
            for (int i = 0; i < 4; i++) {
                int row = warp_m * 64 + i * 16 + arow;
                ldmatrix_x4(afh[i], tAh + (uint32_t)(row * 80 + acol));
                ldmatrix_x4(afl[i], tAl + (uint32_t)(row * 80 + acol));
            }
            int brow = lane & 7;
            int bcol = ks * 32 + 16 * ((lane >> 3) & 1);
            #pragma unroll
            for (int j = 0; j < 8; j++) {
                uint32_t bfh[2], bfl[2];
                int row = warp_n * 64 + j * 8 + brow;
                ldmatrix_x2(bfh, tBh + (uint32_t)(row * 80 + bcol));
                ldmatrix_x2(bfl, tBl + (uint32_t)(row * 80 + bcol));
                #pragma unroll
                for (int i = 0; i < 4; i++) {
                    mma_bf16(acc[i][j], afh[i], bfh);
                    mma_bf16(acc[i][j], afh[i], bfl);
                    mma_bf16(acc[i][j], afl[i], bfh);
                }
            }
        }

        if (it + 1 < KIT) {
            CP_WAIT0();
            __syncthreads();
        }
    }

    // epilogue
    int row0 = by * 128 + warp_m * 64;
    int col0 = bx * 256 + warp_n * 64;
    #pragma unroll
    for (int i = 0; i < 4; i++) {
        int ra = row0 + i * 16 + (lane >> 2);
        #pragma unroll
        for (int j = 0; j < 8; j++) {
            int ca = col0 + j * 8 + (lane & 3) * 2;
            float b0 = bias[ca], b1 = bias[ca + 1];
            float v0 = acc[i][j][0] + b0, v1 = acc[i][j][1] + b1;
            float w0 = acc[i][j][2] + b0, w1 = acc[i][j][3] + b1;
            if (TANH) { v0 = tanhf(v0); v1 = tanhf(v1); w0 = tanhf(w0); w1 = tanhf(w1); }
            if (OUT32) {
                *(float2*)(C32 + (size_t)ra * ldC + ca)       = make_float2(v0, v1);
                *(float2*)(C32 + (size_t)(ra + 8) * ldC + ca) = make_float2(w0, w1);
            }
            if (OUTSPLIT) {
                __nv_bfloat162 h, l;
                split2(v0, v1, h, l);
                *(__nv_bfloat162*)(Chi + (size_t)ra * ldC + ca) = h;
                *(__nv_bfloat162*)(Clo + (size_t)ra * ldC + ca) = l;
                split2(w0, w1, h, l);
                *(__nv_bfloat162*)(Chi + (size_t)(ra + 8) * ldC + ca) = h;
                *(__nv_bfloat162*)(Clo + (size_t)(ra + 8) * ldC + ca) = l;
            }
        }
    }
}

// ===========================================================================
// Distance GEMM: bf16 ldmatrix + mma.
// CTA tile 128(M) x 256(N), 8 warps 2x4, warp 64x64, cp.async double buffer.
// ===========================================================================
__global__ void __launch_bounds__(256) dist_gemm_bf16_kernel(
    const __nv_bfloat16* __restrict__ A,
    const __nv_bfloat16* __restrict__ B,
    float* __restrict__ C)
{
    __shared__ __nv_bfloat16 sA[2][128 * 40];
    __shared__ __nv_bfloat16 sB[2][256 * 40];

    int tid = threadIdx.x;
    int lane = tid & 31;
    int wid = tid >> 5;
    int warp_m = wid >> 2;
    int warp_n = wid & 3;
    int bx = blockIdx.x;      // N tile (256 anchors)
    int by = blockIdx.y;      // M tile (128 src)

    const __nv_bfloat16* Ag = A + (size_t)(by * 128) * D_DIM;
    const __nv_bfloat16* Bg = B + (size_t)(bx * 256) * D_DIM;

    uint32_t a_s[2], b_s[2];
    a_s[0] = (uint32_t)__cvta_generic_to_shared(&sA[0][0]);
    a_s[1] = (uint32_t)__cvta_generic_to_shared(&sA[1][0]);
    b_s[0] = (uint32_t)__cvta_generic_to_shared(&sB[0][0]);
    b_s[1] = (uint32_t)__cvta_generic_to_shared(&sB[1][0]);

    float acc[4][8][4];
    #pragma unroll
    for (int i = 0; i < 4; i++)
        #pragma unroll
        for (int j = 0; j < 8; j++)
            #pragma unroll
            for (int e = 0; e < 4; e++) acc[i][j][e] = 0.f;

    // loader: all threads load B row tid; threads<128 also A row tid
    {
        #pragma unroll
        for (int q = 0; q < 4; q++)
            cp_async16(b_s[0] + (uint32_t)(tid * 80) + q * 16,
                       Bg + (size_t)tid * D_DIM + q * 8);
        if (tid < 128) {
            #pragma unroll
            for (int q = 0; q < 4; q++)
                cp_async16(a_s[0] + (uint32_t)(tid * 80) + q * 16,
                           Ag + (size_t)tid * D_DIM + q * 8);
        }
    }
    CP_COMMIT();
    CP_WAIT0();
    __syncthreads();

    const int KIT = D_DIM / 32;   // 16
    for (int it = 0; it < KIT; it++) {
        int cur = it & 1;
        if (it + 1 < KIT) {
            int kt = (it + 1) * 32;
            #pragma unroll
            for (int q = 0; q < 4; q++)
                cp_async16(b_s[cur ^ 1] + (uint32_t)(tid * 80) + q * 16,
                           Bg + (size_t)tid * D_DIM + kt + q * 8);
            if (tid < 128) {
                #pragma unroll
                for (int q = 0; q < 4; q++)
                    cp_async16(a_s[cur ^ 1] + (uint32_t)(tid * 80) + q * 16,
                               Ag + (size_t)tid * D_DIM + kt + q * 8);
            }
            CP_COMMIT();
        }

        #pragma unroll
        for (int ks = 0; ks < 2; ks++) {
            uint32_t af[4][4];
            int arow = (lane & 7) + 8 * ((lane >> 3) & 1);
            int acol = ks * 32 + 16 * (lane >> 4);
            #pragma unroll
            for (int i = 0; i < 4; i++) {
                int row = warp_m * 64 + i * 16 + arow;
                ldmatrix_x4(af[i], a_s[cur] + (uint32_t)(row * 80 + acol));
            }
            int brow = lane & 7;
            int bcol = ks * 32 + 16 * ((lane >> 3) & 1);
            #pragma unroll
            for (int j = 0; j < 8; j++) {
                uint32_t bf[2];
                int row = warp_n * 64 + j * 8 + brow;
                ldmatrix_x2(bf, b_s[cur] + (uint32_t)(row * 80 + bcol));
                #pragma unroll
                for (int i = 0; i < 4; i++)
                    mma_bf16(acc[i][j], af[i], bf);
            }
        }

        if (it + 1 < KIT) {
            CP_WAIT0();
            __syncthreads();
        }
    }

    int row0 = by * 128 + warp_m * 64;
    int col0 = bx * 256 + warp_n * 64;
    #pragma unroll
    for (int i = 0; i < 4; i++) {
        int ra = row0 + i * 16 + (lane >> 2);
        #pragma unroll
        for (int j = 0; j < 8; j++) {
            int ca = col0 + j * 8 + (lane & 3) * 2;
            *(float2*)(C + (size_t)ra * M_ANC + ca) =
                make_float2(acc[i][j][0], acc[i][j][1]);
            *(float2*)(C + (size_t)(ra + 8) * M_ANC + ca) =
                make_float2(acc[i][j][2], acc[i][j][3]);
        }
    }
}

// ---------------------------------------------------------------------------
// anchor squared norms
// ---------------------------------------------------------------------------
__global__ void anorm_kernel(const float* __restrict__ anchor, float* __restrict__ anorm) {
    int gw = (blockIdx.x * blockDim.x + threadIdx.x) >> 5;
    int lane = threadIdx.x & 31;
    if (gw >= M_ANC) return;
    const float* row = anchor + (size_t)gw * D_DIM;
    float s = 0.f;
    #pragma unroll
    for (int j = lane; j < D_DIM; j += 32) { float v = row[j]; s += v * v; }
    #pragma unroll
    for (int off = 16; off; off >>= 1) s += __shfl_xor_sync(0xffffffffu, s, off);
    if (lane == 0) anorm[gw] = s;
}

// ---------------------------------------------------------------------------
// top-5 with bf16->fp32 refinement (unchanged)
// ---------------------------------------------------------------------------
#define TK_MARGIN 2.5f
#define TK_MAXC   64

__global__ void __launch_bounds__(256) topk_refine_kernel(
    const float* __restrict__ dots,
    const float* __restrict__ anorm,
    const float* __restrict__ src,
    const float* __restrict__ anchor,
    int* __restrict__ idx_out)
{
    __shared__ int   s_cand[8][TK_MAXC];
    __shared__ float s_dval[8][TK_MAXC];

    int w = threadIdx.x >> 5;
    int row = (blockIdx.x * blockDim.x + threadIdx.x) >> 5;
    int lane = threadIdx.x & 31;
    if (row >= N_SRC) return;

    const float* drow = dots + (size_t)row * M_ANC;

    float best[KNN_K];
    int   bidx[KNN_K];
    #pragma unroll
    for (int i = 0; i < KNN_K; i++) { best[i] = FLT_MAX; bidx[i] = 0x7fffffff; }

    for (int m = lane; m < M_ANC; m += 32) {
        float d = anorm[m] - 2.f * drow[m];
        if (d < best[KNN_K - 1]) {
            int p = KNN_K - 1;
            #pragma unroll
            for (int q = KNN_K - 1; q > 0; q--) {
                if (d < best[q - 1]) { best[q] = best[q - 1]; bidx[q] = bidx[q - 1]; p = q - 1; }
            }
            best[p] = d; bidx[p] = m;
        }
    }

    float t5 = FLT_MAX;
    int head = 0;
    #pragma unroll
    for (int s = 0; s < KNN_K; s++) {
        float mv = (head < KNN_K) ? best[head] : FLT_MAX;
        int   mi = (head < KNN_K) ? bidx[head] : 0x7fffffff;
        #pragma unroll
        for (int off = 16; off; off >>= 1) {
            float ov = __shfl_xor_sync(0xffffffffu, mv, off);
            int   oi = __shfl_xor_sync(0xffffffffu, mi, off);
            if (ov < mv || (ov == mv && oi < mi)) { mv = ov; mi = oi; }
        }
        if (head < KNN_K && bidx[head] == mi) head++;
        t5 = mv;
    }
    float thresh = t5 + TK_MARGIN;

    int cnt = 0;
    for (int m = lane; m < M_ANC; m += 32) {
        float d = anorm[m] - 2.f * drow[m];
        bool pred = (d <= thresh);
        unsigned mask = __ballot_sync(0xffffffffu, pred);
        if (pred) {
            int pos = cnt + __popc(mask & ((1u << lane) - 1u));
            if (pos < TK_MAXC) s_cand[w][pos] = m;
        }
        cnt += __popc(mask);
    }
    if (cnt > TK_MAXC) cnt = TK_MAXC;
    __syncwarp();

    float sreg[D_DIM / 32];
    const float* srow = src + (size_t)row * D_DIM;
    #pragma unroll
    for (int j = 0; j < D_DIM / 32; j++) sreg[j] = srow[lane + 32 * j];

    for (int c = 0; c < cnt; c++) {
        int m = s_cand[w][c];
        const float* arow = anchor + (size_t)m * D_DIM;
        float s = 0.f;
        #pragma unroll
        for (int j = 0; j < D_DIM / 32; j++) s += sreg[j] * arow[lane + 32 * j];
        #pragma unroll
        for (int off = 16; off; off >>= 1) s += __shfl_xor_sync(0xffffffffu, s, off);
        if (lane == 0) s_dval[w][c] = anorm[m] - 2.f * s;
    }
    __syncwarp();

    if (lane == 0) {
        #pragma unroll
        for (int s = 0; s < KNN_K; s++) {
            float mv = FLT_MAX; int mi = 0x7fffffff; int mc = -1;
            for (int c = 0; c < cnt; c++) {
                float v = s_dval[w][c]; int id = s_cand[w][c];
                if (v < mv || (v == mv && id < mi)) { mv = v; mi = id; mc = c; }
            }
            idx_out[row * KNN_K + s] = mi;
            if (mc >= 0) s_dval[w][mc] = FLT_MAX;
        }
    }
}

// ---------------------------------------------------------------------------
// gather + mean -> split bf16 output
// ---------------------------------------------------------------------------
__global__ void gather_mean_split_kernel(const float* __restrict__ anchor,
                                         const int* __restrict__ idx,
                                         __nv_bfloat16* __restrict__ yh,
                                         __nv_bfloat16* __restrict__ yl)
{
    int i = blockIdx.x * blockDim.x + threadIdx.x;
    if (i >= N_SRC * (D_DIM / 4)) return;
    int n = i / (D_DIM / 4);
    int d4 = (i % (D_DIM / 4)) * 4;
    const int* ix = idx + n * KNN_K;
    float4 a = make_float4(0.f, 0.f, 0.f, 0.f);
    #pragma unroll
    for (int k = 0; k < KNN_K; k++) {
        float4 v = *(const float4*)(anchor + (size_t)ix[k] * D_DIM + d4);
        a.x += v.x; a.y += v.y; a.z += v.z; a.w += v.w;
    }
    const float inv = 1.f / (float)KNN_K;
    a.x *= inv; a.y *= inv; a.z *= inv; a.w *= inv;
    __nv_bfloat162 h0, l0, h1, l1;
    split2(a.x, a.y, h0, l0);
    split2(a.z, a.w, h1, l1);
    size_t o = (size_t)n * D_DIM + d4;
    *(__nv_bfloat162*)(yh + o)     = h0;
    *(__nv_bfloat162*)(yh + o + 2) = h1;
    *(__nv_bfloat162*)(yl + o)     = l0;
    *(__nv_bfloat162*)(yl + o + 2) = l1;
}

// ---------------------------------------------------------------------------
// BatchNorm
// ---------------------------------------------------------------------------
__global__ void bn_stats_kernel(const float* __restrict__ X,
                                float* __restrict__ ps, float* __restrict__ qs)
{
    int c = threadIdx.x;
    int r0 = blockIdx.x * 128;
    float s = 0.f, q = 0.f;
    #pragma unroll 4
    for (int r = 0; r < 128; r++) {
        float v = X[(size_t)(r0 + r) * D_DIM + c];
        s += v; q += v * v;
    }
    ps[blockIdx.x * D_DIM + c] = s;
    qs[blockIdx.x * D_DIM + c] = q;
}

__global__ void bn_final_kernel(const float* __restrict__ ps, const float* __restrict__ qs,
                                float* __restrict__ mean, float* __restrict__ rstd)
{
    int c = threadIdx.x;
    float s = 0.f, q = 0.f;
    #pragma unroll 8
    for (int b = 0; b < 128; b++) { s += ps[b * D_DIM + c]; q += qs[b * D_DIM + c]; }
    float m = s * (1.f / (float)N_SRC);
    float v = q * (1.f / (float)N_SRC) - m * m;
    mean[c] = m;
    rstd[c] = rsqrtf(v + BN_EPS);
}

template<bool TANH>
__global__ void bn_apply_kernel(const float* __restrict__ X, float* __restrict__ Y,
                                const float* __restrict__ mean, const float* __restrict__ rstd,
                                const float* __restrict__ g, const float* __restrict__ b)
{
    int i = blockIdx.x * blockDim.x + threadIdx.x;
    if (i >= N_SRC * (D_DIM / 4)) return;
    int c0 = (i * 4) & (D_DIM - 1);
    float4 x = *(const float4*)(X + (size_t)i * 4);
    float v0 = (x.x - mean[c0 + 0]) * rstd[c0 + 0] * g[c0 + 0] + b[c0 + 0];
    float v1 = (x.y - mean[c0 + 1]) * rstd[c0 + 1] * g[c0 + 1] + b[c0 + 1];
    float v2 = (x.z - mean[c0 + 2]) * rstd[c0 + 2] * g[c0 + 2] + b[c0 + 2];
    float v3 = (x.w - mean[c0 + 3]) * rstd[c0 + 3] * g[c0 + 3] + b[c0 + 3];
    if (TANH) { v0 = tanhf(v0); v1 = tanhf(v1); v2 = tanhf(v2); v3 = tanhf(v3); }
    *(float4*)(Y + (size_t)i * 4) = make_float4(v0, v1, v2, v3);
}

// BN apply + write fp32 AND split bf16
__global__ void bn_apply_split_kernel(const float* __restrict__ X, float* __restrict__ Y,
                                      __nv_bfloat16* __restrict__ Yh,
                                      __nv_bfloat16* __restrict__ Yl,
                                      const float* __restrict__ mean,
                                      const float* __restrict__ rstd,
                                      const float* __restrict__ g,
                                      const float* __restrict__ b)
{
    int i = blockIdx.x * blockDim.x + threadIdx.x;
    if (i >= N_SRC * (D_DIM / 4)) return;
    int c0 = (i * 4) & (D_DIM - 1);
    float4 x = *(const float4*)(X + (size_t)i * 4);
    float v0 = (x.x - mean[c0 + 0]) * rstd[c0 + 0] * g[c0 + 0] + b[c0 + 0];
    float v1 = (x.y - mean[c0 + 1]) * rstd[c0 + 1] * g[c0 + 1] + b[c0 + 1];
    float v2 = (x.z - mean[c0 + 2]) * rstd[c0 + 2] * g[c0 + 2] + b[c0 + 2];
    float v3 = (x.w - mean[c0 + 3]) * rstd[c0 + 3] * g[c0 + 3] + b[c0 + 3];
    *(float4*)(Y + (size_t)i * 4) = make_float4(v0, v1, v2, v3);
    __nv_bfloat162 h0, l0, h1, l1;
    split2(v0, v1, h0, l0);
    split2(v2, v3, h1, l1);
    *(__nv_bfloat162*)(Yh + (size_t)i * 4)     = h0;
    *(__nv_bfloat162*)(Yh + (size_t)i * 4 + 2) = h1;
    *(__nv_bfloat162*)(Yl + (size_t)i * 4)     = l0;
    *(__nv_bfloat162*)(Yl + (size_t)i * 4 + 2) = l1;
}

__global__ void add_kernel(float* __restrict__ A, const float* __restrict__ B, int n4)
{
    int i = blockIdx.x * blockDim.x + threadIdx.x;
    if (i >= n4) return;
    float4 a = *(float4*)(A + (size_t)i * 4);
    float4 b = *(const float4*)(B + (size_t)i * 4);
    a.x += b.x; a.y += b.y; a.z += b.z; a.w += b.w;
    *(float4*)(A + (size_t)i * 4) = a;
}

// ---------------------------------------------------------------------------
// launch
// ---------------------------------------------------------------------------
extern "C" void kernel_launch(void* const* d_in, const int* in_sizes, int n_in,
                              void* d_out, int out_size)
{
    const float* src    = (const float*)d_in[0];
    const float* anchor = (const float*)d_in[1];
    const float* W_dim  = (const float*)d_in[2];
    const float* b_dim  = (const float*)d_in[3];
    const float* W_fus  = (const float*)d_in[4];
    const float* b_fus  = (const float*)d_in[5];
    const float* W_e1   = (const float*)d_in[6];
    const float* b_e1   = (const float*)d_in[7];
    const float* W_e2   = (const float*)d_in[8];
    const float* b_e2   = (const float*)d_in[9];
    const float* g1     = (const float*)d_in[10];
    const float* bt1    = (const float*)d_in[11];
    const float* g2     = (const float*)d_in[12];
    const float* bt2    = (const float*)d_in[13];
    const float* W_d    = (const float*)d_in[14];
    const float* b_d    = (const float*)d_in[15];
    const float* g_d    = (const float*)d_in[16];
    const float* bt_d   = (const float*)d_in[17];
    float* out = (float*)d_out;

    float *dots, *anorm, *comb, *tbuf, *zbuf, *ps, *qs, *mean, *rstd;
    int* idx;
    __nv_bfloat16 *src_bf, *anc_bf;
    __nv_bfloat16 *catA_hi, *catA_lo, *neigh_hi, *neigh_lo;
    __nv_bfloat16 *comb_hi, *comb_lo, *hid_hi, *hid_lo;
    __nv_bfloat16 *WdimT_hi, *WdimT_lo, *WfusT_hi, *WfusT_lo;
    __nv_bfloat16 *We1T_hi, *We1T_lo, *We2T_hi, *We2T_lo, *WdT_hi, *WdT_lo;

    cudaGetSymbolAddress((void**)&dots,     g_dots);
    cudaGetSymbolAddress((void**)&anorm,    g_anorm);
    cudaGetSymbolAddress((void**)&idx,      g_idx);
    cudaGetSymbolAddress((void**)&comb,     g_comb);
    cudaGetSymbolAddress((void**)&tbuf,     g_tbuf);
    cudaGetSymbolAddress((void**)&zbuf,     g_zbuf);
    cudaGetSymbolAddress((void**)&ps,       g_ps);
    cudaGetSymbolAddress((void**)&qs,       g_qs);
    cudaGetSymbolAddress((void**)&mean,     g_mean);
    cudaGetSymbolAddress((void**)&rstd,     g_rstd);
    cudaGetSymbolAddress((void**)&src_bf,   g_src_bf);
    cudaGetSymbolAddress((void**)&anc_bf,   g_anc_bf);
    cudaGetSymbolAddress((void**)&catA_hi,  g_catA_hi);
    cudaGetSymbolAddress((void**)&catA_lo,  g_catA_lo);
    cudaGetSymbolAddress((void**)&neigh_hi, g_neigh_hi);
    cudaGetSymbolAddress((void**)&neigh_lo, g_neigh_lo);
    cudaGetSymbolAddress((void**)&comb_hi,  g_comb_hi);
    cudaGetSymbolAddress((void**)&comb_lo,  g_comb_lo);
    cudaGetSymbolAddress((void**)&hid_hi,   g_hid_hi);
    cudaGetSymbolAddress((void**)&hid_lo,   g_hid_lo);
    cudaGetSymbolAddress((void**)&WdimT_hi, g_WdimT_hi);
    cudaGetSymbolAddress((void**)&WdimT_lo, g_WdimT_lo);
    cudaGetSymbolAddress((void**)&WfusT_hi, g_WfusT_hi);
    cudaGetSymbolAddress((void**)&WfusT_lo, g_WfusT_lo);
    cudaGetSymbolAddress((void**)&We1T_hi,  g_We1T_hi);
    cudaGetSymbolAddress((void**)&We1T_lo,  g_We1T_lo);
    cudaGetSymbolAddress((void**)&We2T_hi,  g_We2T_hi);
    cudaGetSymbolAddress((void**)&We2T_lo,  g_We2T_lo);
    cudaGetSymbolAddress((void**)&WdT_hi,   g_WdT_hi);
    cudaGetSymbolAddress((void**)&WdT_lo,   g_WdT_lo);

    cudaFuncSetAttribute(gemm_split_kernel<false, false, true>,
                         cudaFuncAttributeMaxDynamicSharedMemorySize, GS_SMEM);
    cudaFuncSetAttribute(gemm_split_kernel<false, true, false>,
                         cudaFuncAttributeMaxDynamicSharedMemorySize, GS_SMEM);
    cudaFuncSetAttribute(gemm_split_kernel<true, false, true>,
                         cudaFuncAttributeMaxDynamicSharedMemorySize, GS_SMEM);

    const int ND4 = N_SRC * (D_DIM / 4);

    // 0. conversions + weight transposes
    tobf16_kernel<<<(N_SRC * D_DIM / 4 + 255) / 256, 256>>>(src, src_bf, N_SRC * D_DIM / 4);
    tobf16_kernel<<<(M_ANC * D_DIM / 4 + 255) / 256, 256>>>(anchor, anc_bf, M_ANC * D_DIM / 4);
    split_src_kernel<<<(ND4 + 255) / 256, 256>>>(src, catA_hi, catA_lo);
    transpose_split_kernel<<<dim3(512 / 32, 512 / 32),  dim3(32, 8)>>>(W_dim, WdimT_hi, WdimT_lo, 512, 512);
    transpose_split_kernel<<<dim3(512 / 32, 1024 / 32), dim3(32, 8)>>>(W_fus, WfusT_hi, WfusT_lo, 1024, 512);
    transpose_split_kernel<<<dim3(2048 / 32, 512 / 32), dim3(32, 8)>>>(W_e1, We1T_hi, We1T_lo, 512, 2048);
    transpose_split_kernel<<<dim3(512 / 32, 2048 / 32), dim3(32, 8)>>>(W_e2, We2T_hi, We2T_lo, 2048, 512);
    transpose_split_kernel<<<dim3(512 / 32, 512 / 32),  dim3(32, 8)>>>(W_d, WdT_hi, WdT_lo, 512, 512);

    // 1. anchor norms
    anorm_kernel<<<(M_ANC * 32 + 255) / 256, 256>>>(anchor, anorm);

    // 2. dots = src @ anchor^T
    dist_gemm_bf16_kernel<<<dim3(M_ANC / 256, N_SRC / 128), 256>>>(src_bf, anc_bf, dots);

    // 3. top-5 with fp32 refinement
    topk_refine_kernel<<<(N_SRC * 32) / 256, 256>>>(dots, anorm, src, anchor, idx);

    // 4. gather + mean -> neigh split
    gather_mean_split_kernel<<<(ND4 + 255) / 256, 256>>>(anchor, idx, neigh_hi, neigh_lo);

    // 5. amap = neigh @ W_dim + b_dim  -> catA cols [512,1024)
    gemm_split_kernel<false, false, true><<<dim3(512 / 256, N_SRC / 128), 256, GS_SMEM>>>(
        neigh_hi, neigh_lo, WdimT_hi, WdimT_lo, b_dim,
        nullptr, catA_hi + 512, catA_lo + 512, 1024, 512, 512);

    // 6. comb = [src|amap] @ W_fus + b_fus   (K=1024)
    gemm_split_kernel<false, true, false><<<dim3(512 / 256, N_SRC / 128), 256, GS_SMEM>>>(
        catA_hi, catA_lo, WfusT_hi, WfusT_lo, b_fus,
        comb, nullptr, nullptr, 512, 512, 1024);

    // 7. BN1 -> comb fp32 + comb split
    bn_stats_kernel<<<128, 512>>>(comb, ps, qs);
    bn_final_kernel<<<1, 512>>>(ps, qs, mean, rstd);
    bn_apply_split_kernel<<<(ND4 + 255) / 256, 256>>>(comb, comb, comb_hi, comb_lo,
                                                      mean, rstd, g1, bt1);

    // 8. hidden = tanh(comb @ W_e1 + b_e1) -> split
    gemm_split_kernel<true, false, true><<<dim3(F_DIM / 256, N_SRC / 128), 256, GS_SMEM>>>(
        comb_hi, comb_lo, We1T_hi, We1T_lo, b_e1,
        nullptr, hid_hi, hid_lo, F_DIM, F_DIM, 512);

    // 9. tbuf = hidden @ W_e2 + b_e2   (K=2048)
    gemm_split_kernel<false, true, false><<<dim3(512 / 256, N_SRC / 128), 256, GS_SMEM>>>(
        hid_hi, hid_lo, We2T_hi, We2T_lo, b_e2,
        tbuf, nullptr, nullptr, 512, 512, F_DIM);

    // 10. comb += tbuf ; BN2 -> comb fp32 + split
    add_kernel<<<(ND4 + 255) / 256, 256>>>(comb, tbuf, ND4);
    bn_stats_kernel<<<128, 512>>>(comb, ps, qs);
    bn_final_kernel<<<1, 512>>>(ps, qs, mean, rstd);
    bn_apply_split_kernel<<<(ND4 + 255) / 256, 256>>>(comb, comb, comb_hi, comb_lo,
                                                      mean, rstd, g2, bt2);

    // 11. zbuf = comb @ W_d + b_d ; out = tanh(BN(zbuf))
    gemm_split_kernel<false, true, false><<<dim3(512 / 256, N_SRC / 128), 256, GS_SMEM>>>(
        comb_hi, comb_lo, WdT_hi, WdT_lo, b_d,
        zbuf, nullptr, nullptr, 512, 512, 512);
    bn_stats_kernel<<<128, 512>>>(zbuf, ps, qs);
    bn_final_kernel<<<1, 512>>>(ps, qs, mean, rstd);
    bn_apply_kernel<true><<<(ND4 + 255) / 256, 256>>>(zbuf, out, mean, rstd, g_d, bt_d);
}